// round 13
// baseline (speedup 1.0000x reference)
#include <cuda_runtime.h>
#include <cuda_bf16.h>
#include <cstdint>
#include <math.h>

#define S_LEN 2048
#define NB    4
#define NH    6
#define HD    128
#define CDIM  768
#define MTOT  (NB * S_LEN)        // 8192 rows
#define KP    (3 * CDIM)          // 2304 = split-K for bf16x3 GEMM
#define GCH   64                  // GEMM K-chunk (bf16 elems)
#define NCH   (KP / GCH)          // 36 chunks
#define QSCALE 0.08838834764831845f

// ---------------------------------------------------------------------------
// Scratch (device globals: allocation-free rule)
// ---------------------------------------------------------------------------
__device__ __nv_bfloat16 g_a1 [(size_t)MTOT * KP];          // A split [8192, 2304]
__device__ __nv_bfloat16 g_wt1[(size_t)(3 * CDIM) * KP];    // W_attn^T split
__device__ __nv_bfloat16 g_wt2[(size_t)CDIM * KP];          // W_proj^T split
__device__ __nv_bfloat16 g_qh [(size_t)MTOT * (3 * CDIM)];  // QKV hi plane
__device__ __nv_bfloat16 g_ql [(size_t)MTOT * (3 * CDIM)];  // QKV lo plane

__device__ __forceinline__ uint32_t smem_u32(const void* p) {
    uint32_t a;
    asm("{ .reg .u64 t; cvta.to.shared.u64 t, %1; cvt.u32.u64 %0, t; }" : "=r"(a) : "l"(p));
    return a;
}
__device__ __forceinline__ void ldm_x4(uint32_t addr, uint32_t& r0, uint32_t& r1,
                                       uint32_t& r2, uint32_t& r3)
{
    asm volatile("ldmatrix.sync.aligned.m8n8.x4.shared.b16 {%0,%1,%2,%3}, [%4];"
                 : "=r"(r0), "=r"(r1), "=r"(r2), "=r"(r3) : "r"(addr));
}
__device__ __forceinline__ void ldm_x4_t(uint32_t addr, uint32_t& r0, uint32_t& r1,
                                         uint32_t& r2, uint32_t& r3)
{
    asm volatile("ldmatrix.sync.aligned.m8n8.x4.trans.shared.b16 {%0,%1,%2,%3}, [%4];"
                 : "=r"(r0), "=r"(r1), "=r"(r2), "=r"(r3) : "r"(addr));
}
__device__ __forceinline__ void mma16816(float* c, const uint32_t* a, const uint32_t* b)
{
    asm volatile(
        "mma.sync.aligned.m16n8k16.row.col.f32.bf16.bf16.f32 "
        "{%0,%1,%2,%3}, {%4,%5,%6,%7}, {%8,%9}, {%0,%1,%2,%3};"
        : "+f"(c[0]), "+f"(c[1]), "+f"(c[2]), "+f"(c[3])
        : "r"(a[0]), "r"(a[1]), "r"(a[2]), "r"(a[3]), "r"(b[0]), "r"(b[1]));
}
__device__ __forceinline__ uint32_t pack_bf(__nv_bfloat16 lo, __nv_bfloat16 hi) {
    __nv_bfloat162 t(lo, hi);
    return *(uint32_t*)&t;
}

// ---------------------------------------------------------------------------
// Split kernels. A' = [Ah|Al|Ah], B' = [Bh|Bh|Bl] => AhBh + AlBh + AhBl
// ---------------------------------------------------------------------------
__global__ void asplit_kernel(const float* __restrict__ src,
                              __nv_bfloat16* __restrict__ dst, int total, int K)
{
    int idx = blockIdx.x * blockDim.x + threadIdx.x;
    if (idx >= total) return;
    int m = idx / K, k = idx - m * K;
    float v = src[idx];
    __nv_bfloat16 h = __float2bfloat16_rn(v);
    __nv_bfloat16 l = __float2bfloat16_rn(v - __bfloat162float(h));
    __nv_bfloat16* d = dst + (size_t)m * (3 * K) + k;
    d[0]     = h;
    d[K]     = l;
    d[2 * K] = h;
}

__global__ void wsplit_kernel(const float* __restrict__ W,
                              __nv_bfloat16* __restrict__ Wt, int K, int N)
{
    __shared__ float t[32][33];
    int kb = blockIdx.x * 32, nb = blockIdx.y * 32;
    int tx = threadIdx.x, ty = threadIdx.y;    // block (32, 8)
    for (int i = ty; i < 32; i += 8)
        t[i][tx] = W[(size_t)(kb + i) * N + nb + tx];
    __syncthreads();
    for (int i = ty; i < 32; i += 8) {
        int n = nb + i, k = kb + tx;
        float v = t[tx][i];
        __nv_bfloat16 h = __float2bfloat16_rn(v);
        __nv_bfloat16 l = __float2bfloat16_rn(v - __bfloat162float(h));
        __nv_bfloat16* d = Wt + (size_t)n * (3 * K) + k;
        d[0]     = h;
        d[K]     = h;
        d[2 * K] = l;
    }
}

// ---------------------------------------------------------------------------
// bf16 mma.sync GEMM, 128x128 CTA tile, 3-stage cp.async, 2 CTA/SM.
// Prefetch for chunk c+2 issued BEFORE the MMA block of chunk c (safe: top
// barrier of iter c guarantees all warps done with stage (c+2)%3 == (c-1)%3),
// giving ~2 compute blocks of load headroom instead of ~1.
// mode 0: C = f32 out (+bias).   mode 1: hi/lo bf16 planes (+bias), Q scaled.
// ---------------------------------------------------------------------------
#define AST 72
#define STAGE_B  (128 * AST * 2)       // 18432 per operand tile
#define GEMM_SMEM (6 * STAGE_B)        // 110592 (3 stages x A,B)

__device__ __forceinline__ void g_load_tile(uint32_t sm_tile,
                                            const __nv_bfloat16* g, int k0, int tid)
{
#pragma unroll
    for (int i = 0; i < 4; i++) {
        int s = i * 256 + tid;
        int r = s >> 3, cg = s & 7;
        uint32_t dst = sm_tile + r * 144 + cg * 16;
        const void* src = g + (size_t)r * KP + k0 + cg * 8;
        asm volatile("cp.async.cg.shared.global [%0], [%1], 16;" :: "r"(dst), "l"(src));
    }
}

__global__ __launch_bounds__(256, 2) void mma_gemm_kernel(
    const __nv_bfloat16* __restrict__ A1, const __nv_bfloat16* __restrict__ Bt,
    const float* __restrict__ bias, float* __restrict__ C,
    __nv_bfloat16* __restrict__ hiP, __nv_bfloat16* __restrict__ loP,
    int Nt, int mode)
{
    extern __shared__ char smem[];
    const uint32_t sb = smem_u32(smem);
    const int tid = threadIdx.x, wid = tid >> 5, lane = tid & 31;
    const int m0 = blockIdx.y << 7, n0 = blockIdx.x << 7;
    const int wm = wid & 1, wn = wid >> 1;

    const __nv_bfloat16* Ag = A1 + (size_t)m0 * KP;
    const __nv_bfloat16* Bg = Bt + (size_t)n0 * KP;

    float acc[4][4][4];
#pragma unroll
    for (int i = 0; i < 4; i++)
#pragma unroll
        for (int j = 0; j < 4; j++)
#pragma unroll
            for (int r = 0; r < 4; r++) acc[i][j][r] = 0.f;

    const int a_row = (wm << 6) + (lane & 15);
    const int a_kof = (lane >> 4) << 3;
    const int b_row = (wn << 5) + (lane & 7) + (((lane >> 3) >> 1) << 3);
    const int b_kof = ((lane >> 3) & 1) << 3;

    // prologue: chunks 0,1 into stages 0,1
    g_load_tile(sb,                       Ag, 0, tid);
    g_load_tile(sb + 3 * STAGE_B,         Bg, 0, tid);
    asm volatile("cp.async.commit_group;" ::: "memory");
    g_load_tile(sb + STAGE_B,             Ag, GCH, tid);
    g_load_tile(sb + 3 * STAGE_B + STAGE_B, Bg, GCH, tid);
    asm volatile("cp.async.commit_group;" ::: "memory");

    int cur = 0, nxt = 2;     // compute stage, stage for chunk c+2
    for (int c = 0; c < NCH; c++) {
        if (c + 1 < NCH) asm volatile("cp.async.wait_group 1;" ::: "memory");
        else             asm volatile("cp.async.wait_group 0;" ::: "memory");
        __syncthreads();

        // prefetch chunk c+2 BEFORE compute of chunk c (stage nxt is free:
        // every warp passed the barrier after computing on it at iter c-1)
        if (c + 2 < NCH) {
            g_load_tile(sb + nxt * STAGE_B,       Ag, (c + 2) * GCH, tid);
            g_load_tile(sb + (3 + nxt) * STAGE_B, Bg, (c + 2) * GCH, tid);
            asm volatile("cp.async.commit_group;" ::: "memory");
        }

        const uint32_t sAc = sb + cur * STAGE_B;
        const uint32_t sBc = sb + (3 + cur) * STAGE_B;
#pragma unroll
        for (int ks = 0; ks < 4; ks++) {
            const int kbase = ks << 4;
            uint32_t a[4][4];
#pragma unroll
            for (int mi = 0; mi < 4; mi++) {
                uint32_t addr = sAc + (uint32_t)(a_row + mi * 16) * 144
                              + (uint32_t)(kbase + a_kof) * 2;
                ldm_x4(addr, a[mi][0], a[mi][1], a[mi][2], a[mi][3]);
            }
            uint32_t b[4][2];
#pragma unroll
            for (int nb2 = 0; nb2 < 2; nb2++) {
                uint32_t addr = sBc + (uint32_t)(b_row + nb2 * 16) * 144
                              + (uint32_t)(kbase + b_kof) * 2;
                uint32_t t0, t1, t2, t3;
                ldm_x4(addr, t0, t1, t2, t3);
                b[nb2 * 2 + 0][0] = t0; b[nb2 * 2 + 0][1] = t1;
                b[nb2 * 2 + 1][0] = t2; b[nb2 * 2 + 1][1] = t3;
            }
#pragma unroll
            for (int mi = 0; mi < 4; mi++)
#pragma unroll
                for (int ni = 0; ni < 4; ni++)
                    mma16816(acc[mi][ni], a[mi], b[ni]);
        }

        cur = (cur == 2) ? 0 : cur + 1;
        nxt = (nxt == 2) ? 0 : nxt + 1;
    }

    const int r_top = m0 + (wm << 6) + (lane >> 2);
    const int c_base = n0 + (wn << 5) + ((lane & 3) << 1);
#pragma unroll
    for (int mi = 0; mi < 4; mi++) {
#pragma unroll
        for (int ni = 0; ni < 4; ni++) {
            const int col = c_base + ni * 8;
            const float b0 = bias[col], b1 = bias[col + 1];
            const int row0 = r_top + mi * 16;
            float v00 = acc[mi][ni][0] + b0, v01 = acc[mi][ni][1] + b1;
            float v10 = acc[mi][ni][2] + b0, v11 = acc[mi][ni][3] + b1;
            if (mode == 0) {
                float2 a0 = { v00, v01 }, a1v = { v10, v11 };
                *(float2*)&C[(size_t)row0 * Nt + col]       = a0;
                *(float2*)&C[(size_t)(row0 + 8) * Nt + col] = a1v;
            } else {
                if (col < CDIM) { v00 *= QSCALE; v01 *= QSCALE; v10 *= QSCALE; v11 *= QSCALE; }
                __nv_bfloat16 h00 = __float2bfloat16_rn(v00), h01 = __float2bfloat16_rn(v01);
                __nv_bfloat16 h10 = __float2bfloat16_rn(v10), h11 = __float2bfloat16_rn(v11);
                uint32_t hp0 = pack_bf(h00, h01), hp1 = pack_bf(h10, h11);
                uint32_t lp0 = pack_bf(__float2bfloat16_rn(v00 - __bfloat162float(h00)),
                                       __float2bfloat16_rn(v01 - __bfloat162float(h01)));
                uint32_t lp1 = pack_bf(__float2bfloat16_rn(v10 - __bfloat162float(h10)),
                                       __float2bfloat16_rn(v11 - __bfloat162float(h11)));
                *(uint32_t*)&hiP[(size_t)row0 * Nt + col]       = hp0;
                *(uint32_t*)&loP[(size_t)row0 * Nt + col]       = lp0;
                *(uint32_t*)&hiP[(size_t)(row0 + 8) * Nt + col] = hp1;
                *(uint32_t*)&loP[(size_t)(row0 + 8) * Nt + col] = lp1;
            }
        }
    }
}

// ---------------------------------------------------------------------------
// Tensor-core flash attention (bf16x3, causal). BM=64, BN=64, 128 threads,
// single KV stage, smem 104.4 KB -> 2 CTA/SM, Qh hoisted. (R12 config, frozen.)
// ---------------------------------------------------------------------------
#define FR_STR  272                        // bytes per smem row (136 bf16)
#define OFF_QH  0
#define OFF_QL  (64 * FR_STR)              // 17408
#define OFF_KV0 (2 * 64 * FR_STR)          // 34816
#define SOFF_KH 0
#define SOFF_KL (64 * FR_STR)
#define SOFF_VH (2 * 64 * FR_STR)
#define SOFF_VL (3 * 64 * FR_STR)
#define FLASH_SMEM (OFF_KV0 + 4 * 64 * FR_STR)  // 104448

// one 64x128 bf16 plane tile: 64 rows x 16 chunks of 16B; 8 chunks/thread
__device__ __forceinline__ void stage_plane64(uint32_t dst,
                                              const __nv_bfloat16* src, int tid)
{
#pragma unroll
    for (int i = 0; i < 8; i++) {
        int s = i * 128 + tid;
        int r = s >> 4, c = s & 15;
        asm volatile("cp.async.cg.shared.global [%0], [%1], 16;"
                     :: "r"(dst + r * FR_STR + c * 16),
                        "l"(src + (size_t)r * (3 * CDIM) + c * 8));
    }
}

__global__ __launch_bounds__(128, 2) void flash_mma_kernel(
    const __nv_bfloat16* __restrict__ qh, const __nv_bfloat16* __restrict__ ql,
    __nv_bfloat16* __restrict__ a1out)
{
    extern __shared__ char smc[];
    const uint32_t sb = smem_u32(smc);
    const int tid = threadIdx.x, w = tid >> 5, lane = tid & 31;
    const int b = blockIdx.y / NH, h = blockIdx.y % NH;
    const int p = gridDim.x - 1 - blockIdx.x;     // heaviest first
    const int qm0 = p << 6;                       // 64 q-rows per CTA

    const __nv_bfloat16* qhB = qh + (size_t)(b * S_LEN) * (3 * CDIM) + h * HD;
    const __nv_bfloat16* qlB = ql + (size_t)(b * S_LEN) * (3 * CDIM) + h * HD;
    const int nkb = p + 1;                        // key blocks of 64

    // prologue: Q tiles (hi+lo, 64 rows) + KV block 0
    {
        const __nv_bfloat16* qsrc_h = qhB + (size_t)qm0 * (3 * CDIM);
        const __nv_bfloat16* qsrc_l = qlB + (size_t)qm0 * (3 * CDIM);
#pragma unroll
        for (int i = 0; i < 8; i++) {
            int s = i * 128 + tid;
            int r = s >> 4, c = s & 15;
            asm volatile("cp.async.cg.shared.global [%0], [%1], 16;"
                         :: "r"(sb + OFF_QH + r * FR_STR + c * 16),
                            "l"(qsrc_h + (size_t)r * (3 * CDIM) + c * 8));
            asm volatile("cp.async.cg.shared.global [%0], [%1], 16;"
                         :: "r"(sb + OFF_QL + r * FR_STR + c * 16),
                            "l"(qsrc_l + (size_t)r * (3 * CDIM) + c * 8));
        }
        const uint32_t st0 = sb + OFF_KV0;
        stage_plane64(st0 + SOFF_KH, qhB + CDIM, tid);
        stage_plane64(st0 + SOFF_KL, qlB + CDIM, tid);
        stage_plane64(st0 + SOFF_VH, qhB + 2 * CDIM, tid);
        stage_plane64(st0 + SOFF_VL, qlB + 2 * CDIM, tid);
        asm volatile("cp.async.commit_group;" ::: "memory");
    }

    float m_i[2] = { -1e30f, -1e30f }, l_i[2] = { 0.f, 0.f };
    float o[16][4];
#pragma unroll
    for (int n = 0; n < 16; n++)
#pragma unroll
        for (int r = 0; r < 4; r++) o[n][r] = 0.f;

    const int a_row = (w << 4) + (lane & 15);
    const int a_k8  = (lane >> 4) << 3;
    const int b_row = (lane & 7) + (((lane >> 3) >> 1) << 3);
    const int b_k8  = ((lane >> 3) & 1) << 3;
    const int v_row = lane & 15;
    const int v_n8  = (lane >> 4) << 3;

    const int row_t = qm0 + (w << 4) + (lane >> 2);
    const int col_q = (lane & 3) << 1;

    // wait for Q (and KV0), then hoist Qh fragments into registers
    asm volatile("cp.async.wait_group 0;" ::: "memory");
    __syncthreads();
    uint32_t aQh[8][4];
#pragma unroll
    for (int kt = 0; kt < 8; kt++) {
        const uint32_t koff = (uint32_t)(kt * 16 + a_k8) * 2;
        ldm_x4(sb + OFF_QH + (uint32_t)a_row * FR_STR + koff,
               aQh[kt][0], aQh[kt][1], aQh[kt][2], aQh[kt][3]);
    }

    const uint32_t st = sb + OFF_KV0;
    for (int kb = 0; kb < nkb; kb++) {
        asm volatile("cp.async.wait_group 0;" ::: "memory");
        __syncthreads();   // KV(kb) visible to all warps

        // ---- S = Q'K'^T (3-term bf16, split accumulator banks), 64x64 ----
        float s[8][4], sb2[8][4];
#pragma unroll
        for (int n = 0; n < 8; n++)
#pragma unroll
            for (int r = 0; r < 4; r++) { s[n][r] = 0.f; sb2[n][r] = 0.f; }

#pragma unroll
        for (int kt = 0; kt < 8; kt++) {
            const uint32_t koff = (uint32_t)(kt * 16 + a_k8) * 2;
            uint32_t aL[4];
            ldm_x4(sb + OFF_QL + (uint32_t)a_row * FR_STR + koff,
                   aL[0], aL[1], aL[2], aL[3]);
            const uint32_t kboff = (uint32_t)(kt * 16 + b_k8) * 2;
#pragma unroll
            for (int nb = 0; nb < 4; nb++) {
                uint32_t h0, h1, h2, h3, u0, u1, u2, u3;
                ldm_x4(st + SOFF_KH + (uint32_t)(nb * 16 + b_row) * FR_STR + kboff,
                       h0, h1, h2, h3);
                ldm_x4(st + SOFF_KL + (uint32_t)(nb * 16 + b_row) * FR_STR + kboff,
                       u0, u1, u2, u3);
                uint32_t bh0[2] = { h0, h1 }, bh1[2] = { h2, h3 };
                uint32_t bl0[2] = { u0, u1 }, bl1[2] = { u2, u3 };
                mma16816(s  [2 * nb],     aQh[kt], bh0);
                mma16816(sb2[2 * nb],     aL,      bh0);
                mma16816(sb2[2 * nb],     aQh[kt], bl0);
                mma16816(s  [2 * nb + 1], aQh[kt], bh1);
                mma16816(sb2[2 * nb + 1], aL,      bh1);
                mma16816(sb2[2 * nb + 1], aQh[kt], bl1);
            }
        }
#pragma unroll
        for (int n = 0; n < 8; n++)
#pragma unroll
            for (int r = 0; r < 4; r++) s[n][r] += sb2[n][r];

        // ---- causal mask (diagonal key block only) ----
        if (kb == p) {
            const int col0 = (kb << 6) + col_q;
#pragma unroll
            for (int n = 0; n < 8; n++) {
                const int c = col0 + n * 8;
                if (c     > row_t)     s[n][0] = -1e30f;
                if (c + 1 > row_t)     s[n][1] = -1e30f;
                if (c     > row_t + 8) s[n][2] = -1e30f;
                if (c + 1 > row_t + 8) s[n][3] = -1e30f;
            }
        }

        // ---- online softmax (fp32) ----
        float alpha[2];
#pragma unroll
        for (int hf = 0; hf < 2; hf++) {
            float mx = -1e30f;
#pragma unroll
            for (int n = 0; n < 8; n++)
                mx = fmaxf(mx, fmaxf(s[n][2 * hf], s[n][2 * hf + 1]));
            mx = fmaxf(mx, __shfl_xor_sync(0xffffffffu, mx, 1));
            mx = fmaxf(mx, __shfl_xor_sync(0xffffffffu, mx, 2));
            const float mnew = fmaxf(m_i[hf], mx);
            alpha[hf] = __expf(m_i[hf] - mnew);
            m_i[hf] = mnew;
            float rs = 0.f;
#pragma unroll
            for (int n = 0; n < 8; n++) {
                s[n][2 * hf]     = __expf(s[n][2 * hf]     - mnew);
                s[n][2 * hf + 1] = __expf(s[n][2 * hf + 1] - mnew);
                rs += s[n][2 * hf] + s[n][2 * hf + 1];
            }
            rs += __shfl_xor_sync(0xffffffffu, rs, 1);
            rs += __shfl_xor_sync(0xffffffffu, rs, 2);
            l_i[hf] = l_i[hf] * alpha[hf] + rs;
        }
#pragma unroll
        for (int n = 0; n < 16; n++) {
            o[n][0] *= alpha[0]; o[n][1] *= alpha[0];
            o[n][2] *= alpha[1]; o[n][3] *= alpha[1];
        }

        // ---- P -> bf16 hi/lo A-fragments ----
        uint32_t aPh[4][4], aPl[4][4];
#pragma unroll
        for (int kt = 0; kt < 4; kt++) {
#pragma unroll
            for (int half = 0; half < 2; half++) {
                const int t = 2 * kt + half;
                __nv_bfloat16 h0 = __float2bfloat16_rn(s[t][0]);
                __nv_bfloat16 h1 = __float2bfloat16_rn(s[t][1]);
                __nv_bfloat16 h2 = __float2bfloat16_rn(s[t][2]);
                __nv_bfloat16 h3 = __float2bfloat16_rn(s[t][3]);
                __nv_bfloat16 l0 = __float2bfloat16_rn(s[t][0] - __bfloat162float(h0));
                __nv_bfloat16 l1 = __float2bfloat16_rn(s[t][1] - __bfloat162float(h1));
                __nv_bfloat16 l2 = __float2bfloat16_rn(s[t][2] - __bfloat162float(h2));
                __nv_bfloat16 l3 = __float2bfloat16_rn(s[t][3] - __bfloat162float(h3));
                aPh[kt][2 * half + 0] = pack_bf(h0, h1);
                aPh[kt][2 * half + 1] = pack_bf(h2, h3);
                aPl[kt][2 * half + 0] = pack_bf(l0, l1);
                aPl[kt][2 * half + 1] = pack_bf(l2, l3);
            }
        }

        // ---- O += P'V' (3-term bf16), k=64 ----
#pragma unroll
        for (int kt = 0; kt < 4; kt++) {
            const uint32_t vro = (uint32_t)(kt * 16 + v_row) * FR_STR;
#pragma unroll
            for (int nv = 0; nv < 8; nv++) {
                const uint32_t noff = (uint32_t)(nv * 16 + v_n8) * 2;
                uint32_t h0, h1, h2, h3, u0, u1, u2, u3;
                ldm_x4_t(st + SOFF_VH + vro + noff, h0, h1, h2, h3);
                ldm_x4_t(st + SOFF_VL + vro + noff, u0, u1, u2, u3);
                uint32_t bh0[2] = { h0, h1 }, bh1[2] = { h2, h3 };
                uint32_t bl0[2] = { u0, u1 }, bl1[2] = { u2, u3 };
                mma16816(o[2 * nv],     aPh[kt], bh0);
                mma16816(o[2 * nv],     aPl[kt], bh0);
                mma16816(o[2 * nv],     aPh[kt], bl0);
                mma16816(o[2 * nv + 1], aPh[kt], bh1);
                mma16816(o[2 * nv + 1], aPl[kt], bh1);
                mma16816(o[2 * nv + 1], aPh[kt], bl1);
            }
        }

        __syncthreads();   // all warps done reading KV(kb)
        if (kb + 1 < nkb) {
            const size_t roff = (size_t)((kb + 1) << 6) * (3 * CDIM);
            stage_plane64(st + SOFF_KH, qhB + roff + CDIM, tid);
            stage_plane64(st + SOFF_KL, qlB + roff + CDIM, tid);
            stage_plane64(st + SOFF_VH, qhB + roff + 2 * CDIM, tid);
            stage_plane64(st + SOFF_VL, qlB + roff + 2 * CDIM, tid);
            asm volatile("cp.async.commit_group;" ::: "memory");
        }
    }

    // ---- epilogue: write O directly in split [hi | lo | hi] layout ----
    const float inv0 = 1.f / l_i[0], inv1 = 1.f / l_i[1];
    __nv_bfloat16* ab = a1out + (size_t)(b * S_LEN) * KP + h * HD;
#pragma unroll
    for (int n = 0; n < 16; n++) {
        const int col = n * 8 + col_q;
        float v00 = o[n][0] * inv0, v01 = o[n][1] * inv0;
        float v10 = o[n][2] * inv1, v11 = o[n][3] * inv1;
        __nv_bfloat16 h00 = __float2bfloat16_rn(v00), h01 = __float2bfloat16_rn(v01);
        __nv_bfloat16 h10 = __float2bfloat16_rn(v10), h11 = __float2bfloat16_rn(v11);
        uint32_t hp0 = pack_bf(h00, h01), hp1 = pack_bf(h10, h11);
        uint32_t lp0 = pack_bf(__float2bfloat16_rn(v00 - __bfloat162float(h00)),
                               __float2bfloat16_rn(v01 - __bfloat162float(h01)));
        uint32_t lp1 = pack_bf(__float2bfloat16_rn(v10 - __bfloat162float(h10)),
                               __float2bfloat16_rn(v11 - __bfloat162float(h11)));
        __nv_bfloat16* p0 = ab + (size_t)row_t * KP + col;
        __nv_bfloat16* p1 = ab + (size_t)(row_t + 8) * KP + col;
        *(uint32_t*)(p0)            = hp0;
        *(uint32_t*)(p0 + CDIM)     = lp0;
        *(uint32_t*)(p0 + 2 * CDIM) = hp0;
        *(uint32_t*)(p1)            = hp1;
        *(uint32_t*)(p1 + CDIM)     = lp1;
        *(uint32_t*)(p1 + 2 * CDIM) = hp1;
    }
}

// ---------------------------------------------------------------------------
extern "C" void kernel_launch(void* const* d_in, const int* in_sizes, int n_in,
                              void* d_out, int out_size)
{
    const float* x      = (const float*)d_in[0];
    const float* w_attn = (const float*)d_in[1];
    const float* b_attn = (const float*)d_in[2];
    const float* w_proj = (const float*)d_in[3];
    const float* b_proj = (const float*)d_in[4];
    float* out = (float*)d_out;

    __nv_bfloat16 *a1 = nullptr, *wt1 = nullptr, *wt2 = nullptr, *qh = nullptr, *ql = nullptr;
    cudaGetSymbolAddress((void**)&a1,  g_a1);
    cudaGetSymbolAddress((void**)&wt1, g_wt1);
    cudaGetSymbolAddress((void**)&wt2, g_wt2);
    cudaGetSymbolAddress((void**)&qh,  g_qh);
    cudaGetSymbolAddress((void**)&ql,  g_ql);

    cudaFuncSetAttribute(mma_gemm_kernel,
                         cudaFuncAttributeMaxDynamicSharedMemorySize, GEMM_SMEM);
    cudaFuncSetAttribute(flash_mma_kernel,
                         cudaFuncAttributeMaxDynamicSharedMemorySize, FLASH_SMEM);

    // --- Stage 1: QKV = x @ w_attn + b -> hi/lo planes (Q pre-scaled) ---
    asplit_kernel<<<(MTOT * CDIM + 255) / 256, 256>>>(x, a1, MTOT * CDIM, CDIM);
    {
        dim3 gt(CDIM / 32, (3 * CDIM) / 32), bt(32, 8);
        wsplit_kernel<<<gt, bt>>>(w_attn, wt1, CDIM, 3 * CDIM);
    }
    {
        dim3 g(3 * CDIM / 128, MTOT / 128);
        mma_gemm_kernel<<<g, 256, GEMM_SMEM>>>(a1, wt1, b_attn, nullptr,
                                               qh, ql, 3 * CDIM, 1);
    }

    // --- Stage 2: causal flash attention (bf16x3), BN=64, 2 CTA/SM ---
    {
        dim3 g(S_LEN / 64, NB * NH);
        flash_mma_kernel<<<g, 128, FLASH_SMEM>>>(qh, ql, a1);
    }

    // --- Stage 3: out = att @ w_proj + b (att already split in a1) ---
    {
        dim3 gt(CDIM / 32, CDIM / 32), bt(32, 8);
        wsplit_kernel<<<gt, bt>>>(w_proj, wt2, CDIM, CDIM);
    }
    {
        dim3 g(CDIM / 128, MTOT / 128);
        mma_gemm_kernel<<<g, 256, GEMM_SMEM>>>(a1, wt2, b_proj, out,
                                               nullptr, nullptr, CDIM, 0);
    }
}

// round 14
// speedup vs baseline: 1.0516x; 1.0516x over previous
#include <cuda_runtime.h>
#include <cuda_bf16.h>
#include <cstdint>
#include <math.h>

#define S_LEN 2048
#define NB    4
#define NH    6
#define HD    128
#define CDIM  768
#define MTOT  (NB * S_LEN)        // 8192 rows
#define KP    (3 * CDIM)          // 2304 = split-K for bf16x3 GEMM
#define GCH   64                  // GEMM K-chunk (bf16 elems)
#define NCH   (KP / GCH)          // 36 chunks
#define QSCALE 0.08838834764831845f

// ---------------------------------------------------------------------------
// Scratch (device globals: allocation-free rule)
// ---------------------------------------------------------------------------
__device__ __nv_bfloat16 g_a1 [(size_t)MTOT * KP];          // A split [8192, 2304]
__device__ __nv_bfloat16 g_wt1[(size_t)(3 * CDIM) * KP];    // W_attn^T split
__device__ __nv_bfloat16 g_wt2[(size_t)CDIM * KP];          // W_proj^T split
__device__ __nv_bfloat16 g_qh [(size_t)MTOT * (3 * CDIM)];  // QKV hi plane
__device__ __nv_bfloat16 g_ql [(size_t)MTOT * (3 * CDIM)];  // QKV lo plane

__device__ __forceinline__ uint32_t smem_u32(const void* p) {
    uint32_t a;
    asm("{ .reg .u64 t; cvta.to.shared.u64 t, %1; cvt.u32.u64 %0, t; }" : "=r"(a) : "l"(p));
    return a;
}
__device__ __forceinline__ void ldm_x4(uint32_t addr, uint32_t& r0, uint32_t& r1,
                                       uint32_t& r2, uint32_t& r3)
{
    asm volatile("ldmatrix.sync.aligned.m8n8.x4.shared.b16 {%0,%1,%2,%3}, [%4];"
                 : "=r"(r0), "=r"(r1), "=r"(r2), "=r"(r3) : "r"(addr));
}
__device__ __forceinline__ void ldm_x4_t(uint32_t addr, uint32_t& r0, uint32_t& r1,
                                         uint32_t& r2, uint32_t& r3)
{
    asm volatile("ldmatrix.sync.aligned.m8n8.x4.trans.shared.b16 {%0,%1,%2,%3}, [%4];"
                 : "=r"(r0), "=r"(r1), "=r"(r2), "=r"(r3) : "r"(addr));
}
__device__ __forceinline__ void mma16816(float* c, const uint32_t* a, const uint32_t* b)
{
    asm volatile(
        "mma.sync.aligned.m16n8k16.row.col.f32.bf16.bf16.f32 "
        "{%0,%1,%2,%3}, {%4,%5,%6,%7}, {%8,%9}, {%0,%1,%2,%3};"
        : "+f"(c[0]), "+f"(c[1]), "+f"(c[2]), "+f"(c[3])
        : "r"(a[0]), "r"(a[1]), "r"(a[2]), "r"(a[3]), "r"(b[0]), "r"(b[1]));
}
__device__ __forceinline__ uint32_t pack_bf(__nv_bfloat16 lo, __nv_bfloat16 hi) {
    __nv_bfloat162 t(lo, hi);
    return *(uint32_t*)&t;
}

// ---------------------------------------------------------------------------
// Split kernels. A' = [Ah|Al|Ah], B' = [Bh|Bh|Bl] => AhBh + AlBh + AhBl
// ---------------------------------------------------------------------------
__global__ void asplit_kernel(const float* __restrict__ src,
                              __nv_bfloat16* __restrict__ dst, int total, int K)
{
    int idx = blockIdx.x * blockDim.x + threadIdx.x;
    if (idx >= total) return;
    int m = idx / K, k = idx - m * K;
    float v = src[idx];
    __nv_bfloat16 h = __float2bfloat16_rn(v);
    __nv_bfloat16 l = __float2bfloat16_rn(v - __bfloat162float(h));
    __nv_bfloat16* d = dst + (size_t)m * (3 * K) + k;
    d[0]     = h;
    d[K]     = l;
    d[2 * K] = h;
}

__global__ void wsplit_kernel(const float* __restrict__ W,
                              __nv_bfloat16* __restrict__ Wt, int K, int N)
{
    __shared__ float t[32][33];
    int kb = blockIdx.x * 32, nb = blockIdx.y * 32;
    int tx = threadIdx.x, ty = threadIdx.y;    // block (32, 8)
    for (int i = ty; i < 32; i += 8)
        t[i][tx] = W[(size_t)(kb + i) * N + nb + tx];
    __syncthreads();
    for (int i = ty; i < 32; i += 8) {
        int n = nb + i, k = kb + tx;
        float v = t[tx][i];
        __nv_bfloat16 h = __float2bfloat16_rn(v);
        __nv_bfloat16 l = __float2bfloat16_rn(v - __bfloat162float(h));
        __nv_bfloat16* d = Wt + (size_t)n * (3 * K) + k;
        d[0]     = h;
        d[K]     = h;
        d[2 * K] = l;
    }
}

// ---------------------------------------------------------------------------
// bf16 mma.sync GEMM, 128x128 CTA tile, 3-stage cp.async, 2 CTA/SM.
// Trailing prefetch (issued AFTER the MMA block — measured best placement).
// mode 0: C = f32 out (+bias).   mode 1: hi/lo bf16 planes (+bias), Q scaled.
// ---------------------------------------------------------------------------
#define AST 72
#define STAGE_B  (128 * AST * 2)       // 18432 per operand tile
#define GEMM_SMEM (6 * STAGE_B)        // 110592 (3 stages x A,B)

__device__ __forceinline__ void g_load_tile(uint32_t sm_tile,
                                            const __nv_bfloat16* g, int k0, int tid)
{
#pragma unroll
    for (int i = 0; i < 4; i++) {
        int s = i * 256 + tid;
        int r = s >> 3, cg = s & 7;
        uint32_t dst = sm_tile + r * 144 + cg * 16;
        const void* src = g + (size_t)r * KP + k0 + cg * 8;
        asm volatile("cp.async.cg.shared.global [%0], [%1], 16;" :: "r"(dst), "l"(src));
    }
}

__global__ __launch_bounds__(256, 2) void mma_gemm_kernel(
    const __nv_bfloat16* __restrict__ A1, const __nv_bfloat16* __restrict__ Bt,
    const float* __restrict__ bias, float* __restrict__ C,
    __nv_bfloat16* __restrict__ hiP, __nv_bfloat16* __restrict__ loP,
    int Nt, int mode)
{
    extern __shared__ char smem[];
    const uint32_t sb = smem_u32(smem);
    const int tid = threadIdx.x, wid = tid >> 5, lane = tid & 31;
    const int m0 = blockIdx.y << 7, n0 = blockIdx.x << 7;
    const int wm = wid & 1, wn = wid >> 1;

    const __nv_bfloat16* Ag = A1 + (size_t)m0 * KP;
    const __nv_bfloat16* Bg = Bt + (size_t)n0 * KP;

    float acc[4][4][4];
#pragma unroll
    for (int i = 0; i < 4; i++)
#pragma unroll
        for (int j = 0; j < 4; j++)
#pragma unroll
            for (int r = 0; r < 4; r++) acc[i][j][r] = 0.f;

    const int a_row = (wm << 6) + (lane & 15);
    const int a_kof = (lane >> 4) << 3;
    const int b_row = (wn << 5) + (lane & 7) + (((lane >> 3) >> 1) << 3);
    const int b_kof = ((lane >> 3) & 1) << 3;

    // prologue: chunks 0,1 into stages 0,1
    g_load_tile(sb,                       Ag, 0, tid);
    g_load_tile(sb + 3 * STAGE_B,         Bg, 0, tid);
    asm volatile("cp.async.commit_group;" ::: "memory");
    g_load_tile(sb + STAGE_B,             Ag, GCH, tid);
    g_load_tile(sb + 3 * STAGE_B + STAGE_B, Bg, GCH, tid);
    asm volatile("cp.async.commit_group;" ::: "memory");

    int cur = 0, nxt = 2;     // compute stage, stage for chunk c+2
    for (int c = 0; c < NCH; c++) {
        if (c + 1 < NCH) asm volatile("cp.async.wait_group 1;" ::: "memory");
        else             asm volatile("cp.async.wait_group 0;" ::: "memory");
        __syncthreads();

        const uint32_t sAc = sb + cur * STAGE_B;
        const uint32_t sBc = sb + (3 + cur) * STAGE_B;
#pragma unroll
        for (int ks = 0; ks < 4; ks++) {
            const int kbase = ks << 4;
            uint32_t a[4][4];
#pragma unroll
            for (int mi = 0; mi < 4; mi++) {
                uint32_t addr = sAc + (uint32_t)(a_row + mi * 16) * 144
                              + (uint32_t)(kbase + a_kof) * 2;
                ldm_x4(addr, a[mi][0], a[mi][1], a[mi][2], a[mi][3]);
            }
            uint32_t b[4][2];
#pragma unroll
            for (int nb2 = 0; nb2 < 2; nb2++) {
                uint32_t addr = sBc + (uint32_t)(b_row + nb2 * 16) * 144
                              + (uint32_t)(kbase + b_kof) * 2;
                uint32_t t0, t1, t2, t3;
                ldm_x4(addr, t0, t1, t2, t3);
                b[nb2 * 2 + 0][0] = t0; b[nb2 * 2 + 0][1] = t1;
                b[nb2 * 2 + 1][0] = t2; b[nb2 * 2 + 1][1] = t3;
            }
#pragma unroll
            for (int mi = 0; mi < 4; mi++)
#pragma unroll
                for (int ni = 0; ni < 4; ni++)
                    mma16816(acc[mi][ni], a[mi], b[ni]);
        }

        if (c + 2 < NCH) {
            g_load_tile(sb + nxt * STAGE_B,       Ag, (c + 2) * GCH, tid);
            g_load_tile(sb + (3 + nxt) * STAGE_B, Bg, (c + 2) * GCH, tid);
            asm volatile("cp.async.commit_group;" ::: "memory");
        }
        cur = (cur == 2) ? 0 : cur + 1;
        nxt = (nxt == 2) ? 0 : nxt + 1;
    }

    const int r_top = m0 + (wm << 6) + (lane >> 2);
    const int c_base = n0 + (wn << 5) + ((lane & 3) << 1);
#pragma unroll
    for (int mi = 0; mi < 4; mi++) {
#pragma unroll
        for (int ni = 0; ni < 4; ni++) {
            const int col = c_base + ni * 8;
            const float b0 = bias[col], b1 = bias[col + 1];
            const int row0 = r_top + mi * 16;
            float v00 = acc[mi][ni][0] + b0, v01 = acc[mi][ni][1] + b1;
            float v10 = acc[mi][ni][2] + b0, v11 = acc[mi][ni][3] + b1;
            if (mode == 0) {
                float2 a0 = { v00, v01 }, a1v = { v10, v11 };
                *(float2*)&C[(size_t)row0 * Nt + col]       = a0;
                *(float2*)&C[(size_t)(row0 + 8) * Nt + col] = a1v;
            } else {
                if (col < CDIM) { v00 *= QSCALE; v01 *= QSCALE; v10 *= QSCALE; v11 *= QSCALE; }
                __nv_bfloat16 h00 = __float2bfloat16_rn(v00), h01 = __float2bfloat16_rn(v01);
                __nv_bfloat16 h10 = __float2bfloat16_rn(v10), h11 = __float2bfloat16_rn(v11);
                uint32_t hp0 = pack_bf(h00, h01), hp1 = pack_bf(h10, h11);
                uint32_t lp0 = pack_bf(__float2bfloat16_rn(v00 - __bfloat162float(h00)),
                                       __float2bfloat16_rn(v01 - __bfloat162float(h01)));
                uint32_t lp1 = pack_bf(__float2bfloat16_rn(v10 - __bfloat162float(h10)),
                                       __float2bfloat16_rn(v11 - __bfloat162float(h11)));
                *(uint32_t*)&hiP[(size_t)row0 * Nt + col]       = hp0;
                *(uint32_t*)&loP[(size_t)row0 * Nt + col]       = lp0;
                *(uint32_t*)&hiP[(size_t)(row0 + 8) * Nt + col] = hp1;
                *(uint32_t*)&loP[(size_t)(row0 + 8) * Nt + col] = lp1;
            }
        }
    }
}

// ---------------------------------------------------------------------------
// Tensor-core flash attention (bf16x3, causal). BM=64, BN=64, 128 threads,
// single KV stage, smem 104.4 KB -> 2 CTA/SM, Qh hoisted. (R12 config, frozen.)
// ---------------------------------------------------------------------------
#define FR_STR  272                        // bytes per smem row (136 bf16)
#define OFF_QH  0
#define OFF_QL  (64 * FR_STR)              // 17408
#define OFF_KV0 (2 * 64 * FR_STR)          // 34816
#define SOFF_KH 0
#define SOFF_KL (64 * FR_STR)
#define SOFF_VH (2 * 64 * FR_STR)
#define SOFF_VL (3 * 64 * FR_STR)
#define FLASH_SMEM (OFF_KV0 + 4 * 64 * FR_STR)  // 104448

// one 64x128 bf16 plane tile: 64 rows x 16 chunks of 16B; 8 chunks/thread
__device__ __forceinline__ void stage_plane64(uint32_t dst,
                                              const __nv_bfloat16* src, int tid)
{
#pragma unroll
    for (int i = 0; i < 8; i++) {
        int s = i * 128 + tid;
        int r = s >> 4, c = s & 15;
        asm volatile("cp.async.cg.shared.global [%0], [%1], 16;"
                     :: "r"(dst + r * FR_STR + c * 16),
                        "l"(src + (size_t)r * (3 * CDIM) + c * 8));
    }
}

__global__ __launch_bounds__(128, 2) void flash_mma_kernel(
    const __nv_bfloat16* __restrict__ qh, const __nv_bfloat16* __restrict__ ql,
    __nv_bfloat16* __restrict__ a1out)
{
    extern __shared__ char smc[];
    const uint32_t sb = smem_u32(smc);
    const int tid = threadIdx.x, w = tid >> 5, lane = tid & 31;
    const int b = blockIdx.y / NH, h = blockIdx.y % NH;
    const int p = gridDim.x - 1 - blockIdx.x;     // heaviest first
    const int qm0 = p << 6;                       // 64 q-rows per CTA

    const __nv_bfloat16* qhB = qh + (size_t)(b * S_LEN) * (3 * CDIM) + h * HD;
    const __nv_bfloat16* qlB = ql + (size_t)(b * S_LEN) * (3 * CDIM) + h * HD;
    const int nkb = p + 1;                        // key blocks of 64

    // prologue: Q tiles (hi+lo, 64 rows) + KV block 0
    {
        const __nv_bfloat16* qsrc_h = qhB + (size_t)qm0 * (3 * CDIM);
        const __nv_bfloat16* qsrc_l = qlB + (size_t)qm0 * (3 * CDIM);
#pragma unroll
        for (int i = 0; i < 8; i++) {
            int s = i * 128 + tid;
            int r = s >> 4, c = s & 15;
            asm volatile("cp.async.cg.shared.global [%0], [%1], 16;"
                         :: "r"(sb + OFF_QH + r * FR_STR + c * 16),
                            "l"(qsrc_h + (size_t)r * (3 * CDIM) + c * 8));
            asm volatile("cp.async.cg.shared.global [%0], [%1], 16;"
                         :: "r"(sb + OFF_QL + r * FR_STR + c * 16),
                            "l"(qsrc_l + (size_t)r * (3 * CDIM) + c * 8));
        }
        const uint32_t st0 = sb + OFF_KV0;
        stage_plane64(st0 + SOFF_KH, qhB + CDIM, tid);
        stage_plane64(st0 + SOFF_KL, qlB + CDIM, tid);
        stage_plane64(st0 + SOFF_VH, qhB + 2 * CDIM, tid);
        stage_plane64(st0 + SOFF_VL, qlB + 2 * CDIM, tid);
        asm volatile("cp.async.commit_group;" ::: "memory");
    }

    float m_i[2] = { -1e30f, -1e30f }, l_i[2] = { 0.f, 0.f };
    float o[16][4];
#pragma unroll
    for (int n = 0; n < 16; n++)
#pragma unroll
        for (int r = 0; r < 4; r++) o[n][r] = 0.f;

    const int a_row = (w << 4) + (lane & 15);
    const int a_k8  = (lane >> 4) << 3;
    const int b_row = (lane & 7) + (((lane >> 3) >> 1) << 3);
    const int b_k8  = ((lane >> 3) & 1) << 3;
    const int v_row = lane & 15;
    const int v_n8  = (lane >> 4) << 3;

    const int row_t = qm0 + (w << 4) + (lane >> 2);
    const int col_q = (lane & 3) << 1;

    // wait for Q (and KV0), then hoist Qh fragments into registers
    asm volatile("cp.async.wait_group 0;" ::: "memory");
    __syncthreads();
    uint32_t aQh[8][4];
#pragma unroll
    for (int kt = 0; kt < 8; kt++) {
        const uint32_t koff = (uint32_t)(kt * 16 + a_k8) * 2;
        ldm_x4(sb + OFF_QH + (uint32_t)a_row * FR_STR + koff,
               aQh[kt][0], aQh[kt][1], aQh[kt][2], aQh[kt][3]);
    }

    const uint32_t st = sb + OFF_KV0;
    for (int kb = 0; kb < nkb; kb++) {
        asm volatile("cp.async.wait_group 0;" ::: "memory");
        __syncthreads();   // KV(kb) visible to all warps

        // ---- S = Q'K'^T (3-term bf16, split accumulator banks), 64x64 ----
        float s[8][4], sb2[8][4];
#pragma unroll
        for (int n = 0; n < 8; n++)
#pragma unroll
            for (int r = 0; r < 4; r++) { s[n][r] = 0.f; sb2[n][r] = 0.f; }

#pragma unroll
        for (int kt = 0; kt < 8; kt++) {
            const uint32_t koff = (uint32_t)(kt * 16 + a_k8) * 2;
            uint32_t aL[4];
            ldm_x4(sb + OFF_QL + (uint32_t)a_row * FR_STR + koff,
                   aL[0], aL[1], aL[2], aL[3]);
            const uint32_t kboff = (uint32_t)(kt * 16 + b_k8) * 2;
#pragma unroll
            for (int nb = 0; nb < 4; nb++) {
                uint32_t h0, h1, h2, h3, u0, u1, u2, u3;
                ldm_x4(st + SOFF_KH + (uint32_t)(nb * 16 + b_row) * FR_STR + kboff,
                       h0, h1, h2, h3);
                ldm_x4(st + SOFF_KL + (uint32_t)(nb * 16 + b_row) * FR_STR + kboff,
                       u0, u1, u2, u3);
                uint32_t bh0[2] = { h0, h1 }, bh1[2] = { h2, h3 };
                uint32_t bl0[2] = { u0, u1 }, bl1[2] = { u2, u3 };
                mma16816(s  [2 * nb],     aQh[kt], bh0);
                mma16816(sb2[2 * nb],     aL,      bh0);
                mma16816(sb2[2 * nb],     aQh[kt], bl0);
                mma16816(s  [2 * nb + 1], aQh[kt], bh1);
                mma16816(sb2[2 * nb + 1], aL,      bh1);
                mma16816(sb2[2 * nb + 1], aQh[kt], bl1);
            }
        }
#pragma unroll
        for (int n = 0; n < 8; n++)
#pragma unroll
            for (int r = 0; r < 4; r++) s[n][r] += sb2[n][r];

        // ---- causal mask (diagonal key block only) ----
        if (kb == p) {
            const int col0 = (kb << 6) + col_q;
#pragma unroll
            for (int n = 0; n < 8; n++) {
                const int c = col0 + n * 8;
                if (c     > row_t)     s[n][0] = -1e30f;
                if (c + 1 > row_t)     s[n][1] = -1e30f;
                if (c     > row_t + 8) s[n][2] = -1e30f;
                if (c + 1 > row_t + 8) s[n][3] = -1e30f;
            }
        }

        // ---- online softmax (fp32) ----
        float alpha[2];
#pragma unroll
        for (int hf = 0; hf < 2; hf++) {
            float mx = -1e30f;
#pragma unroll
            for (int n = 0; n < 8; n++)
                mx = fmaxf(mx, fmaxf(s[n][2 * hf], s[n][2 * hf + 1]));
            mx = fmaxf(mx, __shfl_xor_sync(0xffffffffu, mx, 1));
            mx = fmaxf(mx, __shfl_xor_sync(0xffffffffu, mx, 2));
            const float mnew = fmaxf(m_i[hf], mx);
            alpha[hf] = __expf(m_i[hf] - mnew);
            m_i[hf] = mnew;
            float rs = 0.f;
#pragma unroll
            for (int n = 0; n < 8; n++) {
                s[n][2 * hf]     = __expf(s[n][2 * hf]     - mnew);
                s[n][2 * hf + 1] = __expf(s[n][2 * hf + 1] - mnew);
                rs += s[n][2 * hf] + s[n][2 * hf + 1];
            }
            rs += __shfl_xor_sync(0xffffffffu, rs, 1);
            rs += __shfl_xor_sync(0xffffffffu, rs, 2);
            l_i[hf] = l_i[hf] * alpha[hf] + rs;
        }
#pragma unroll
        for (int n = 0; n < 16; n++) {
            o[n][0] *= alpha[0]; o[n][1] *= alpha[0];
            o[n][2] *= alpha[1]; o[n][3] *= alpha[1];
        }

        // ---- P -> bf16 hi/lo A-fragments ----
        uint32_t aPh[4][4], aPl[4][4];
#pragma unroll
        for (int kt = 0; kt < 4; kt++) {
#pragma unroll
            for (int half = 0; half < 2; half++) {
                const int t = 2 * kt + half;
                __nv_bfloat16 h0 = __float2bfloat16_rn(s[t][0]);
                __nv_bfloat16 h1 = __float2bfloat16_rn(s[t][1]);
                __nv_bfloat16 h2 = __float2bfloat16_rn(s[t][2]);
                __nv_bfloat16 h3 = __float2bfloat16_rn(s[t][3]);
                __nv_bfloat16 l0 = __float2bfloat16_rn(s[t][0] - __bfloat162float(h0));
                __nv_bfloat16 l1 = __float2bfloat16_rn(s[t][1] - __bfloat162float(h1));
                __nv_bfloat16 l2 = __float2bfloat16_rn(s[t][2] - __bfloat162float(h2));
                __nv_bfloat16 l3 = __float2bfloat16_rn(s[t][3] - __bfloat162float(h3));
                aPh[kt][2 * half + 0] = pack_bf(h0, h1);
                aPh[kt][2 * half + 1] = pack_bf(h2, h3);
                aPl[kt][2 * half + 0] = pack_bf(l0, l1);
                aPl[kt][2 * half + 1] = pack_bf(l2, l3);
            }
        }

        // ---- O += P'V' (3-term bf16), k=64 ----
#pragma unroll
        for (int kt = 0; kt < 4; kt++) {
            const uint32_t vro = (uint32_t)(kt * 16 + v_row) * FR_STR;
#pragma unroll
            for (int nv = 0; nv < 8; nv++) {
                const uint32_t noff = (uint32_t)(nv * 16 + v_n8) * 2;
                uint32_t h0, h1, h2, h3, u0, u1, u2, u3;
                ldm_x4_t(st + SOFF_VH + vro + noff, h0, h1, h2, h3);
                ldm_x4_t(st + SOFF_VL + vro + noff, u0, u1, u2, u3);
                uint32_t bh0[2] = { h0, h1 }, bh1[2] = { h2, h3 };
                uint32_t bl0[2] = { u0, u1 }, bl1[2] = { u2, u3 };
                mma16816(o[2 * nv],     aPh[kt], bh0);
                mma16816(o[2 * nv],     aPl[kt], bh0);
                mma16816(o[2 * nv],     aPh[kt], bl0);
                mma16816(o[2 * nv + 1], aPh[kt], bh1);
                mma16816(o[2 * nv + 1], aPl[kt], bh1);
                mma16816(o[2 * nv + 1], aPh[kt], bl1);
            }
        }

        __syncthreads();   // all warps done reading KV(kb)
        if (kb + 1 < nkb) {
            const size_t roff = (size_t)((kb + 1) << 6) * (3 * CDIM);
            stage_plane64(st + SOFF_KH, qhB + roff + CDIM, tid);
            stage_plane64(st + SOFF_KL, qlB + roff + CDIM, tid);
            stage_plane64(st + SOFF_VH, qhB + roff + 2 * CDIM, tid);
            stage_plane64(st + SOFF_VL, qlB + roff + 2 * CDIM, tid);
            asm volatile("cp.async.commit_group;" ::: "memory");
        }
    }

    // ---- epilogue: write O directly in split [hi | lo | hi] layout ----
    const float inv0 = 1.f / l_i[0], inv1 = 1.f / l_i[1];
    __nv_bfloat16* ab = a1out + (size_t)(b * S_LEN) * KP + h * HD;
#pragma unroll
    for (int n = 0; n < 16; n++) {
        const int col = n * 8 + col_q;
        float v00 = o[n][0] * inv0, v01 = o[n][1] * inv0;
        float v10 = o[n][2] * inv1, v11 = o[n][3] * inv1;
        __nv_bfloat16 h00 = __float2bfloat16_rn(v00), h01 = __float2bfloat16_rn(v01);
        __nv_bfloat16 h10 = __float2bfloat16_rn(v10), h11 = __float2bfloat16_rn(v11);
        uint32_t hp0 = pack_bf(h00, h01), hp1 = pack_bf(h10, h11);
        uint32_t lp0 = pack_bf(__float2bfloat16_rn(v00 - __bfloat162float(h00)),
                               __float2bfloat16_rn(v01 - __bfloat162float(h01)));
        uint32_t lp1 = pack_bf(__float2bfloat16_rn(v10 - __bfloat162float(h10)),
                               __float2bfloat16_rn(v11 - __bfloat162float(h11)));
        __nv_bfloat16* p0 = ab + (size_t)row_t * KP + col;
        __nv_bfloat16* p1 = ab + (size_t)(row_t + 8) * KP + col;
        *(uint32_t*)(p0)            = hp0;
        *(uint32_t*)(p0 + CDIM)     = lp0;
        *(uint32_t*)(p0 + 2 * CDIM) = hp0;
        *(uint32_t*)(p1)            = hp1;
        *(uint32_t*)(p1 + CDIM)     = lp1;
        *(uint32_t*)(p1 + 2 * CDIM) = hp1;
    }
}

// ---------------------------------------------------------------------------
extern "C" void kernel_launch(void* const* d_in, const int* in_sizes, int n_in,
                              void* d_out, int out_size)
{
    const float* x      = (const float*)d_in[0];
    const float* w_attn = (const float*)d_in[1];
    const float* b_attn = (const float*)d_in[2];
    const float* w_proj = (const float*)d_in[3];
    const float* b_proj = (const float*)d_in[4];
    float* out = (float*)d_out;

    __nv_bfloat16 *a1 = nullptr, *wt1 = nullptr, *wt2 = nullptr, *qh = nullptr, *ql = nullptr;
    cudaGetSymbolAddress((void**)&a1,  g_a1);
    cudaGetSymbolAddress((void**)&wt1, g_wt1);
    cudaGetSymbolAddress((void**)&wt2, g_wt2);
    cudaGetSymbolAddress((void**)&qh,  g_qh);
    cudaGetSymbolAddress((void**)&ql,  g_ql);

    cudaFuncSetAttribute(mma_gemm_kernel,
                         cudaFuncAttributeMaxDynamicSharedMemorySize, GEMM_SMEM);
    cudaFuncSetAttribute(flash_mma_kernel,
                         cudaFuncAttributeMaxDynamicSharedMemorySize, FLASH_SMEM);

    // --- Stage 1: QKV = x @ w_attn + b -> hi/lo planes (Q pre-scaled) ---
    asplit_kernel<<<(MTOT * CDIM + 255) / 256, 256>>>(x, a1, MTOT * CDIM, CDIM);
    {
        dim3 gt(CDIM / 32, (3 * CDIM) / 32), bt(32, 8);
        wsplit_kernel<<<gt, bt>>>(w_attn, wt1, CDIM, 3 * CDIM);
    }
    {
        dim3 g(3 * CDIM / 128, MTOT / 128);
        mma_gemm_kernel<<<g, 256, GEMM_SMEM>>>(a1, wt1, b_attn, nullptr,
                                               qh, ql, 3 * CDIM, 1);
    }

    // --- Stage 2: causal flash attention (bf16x3), BN=64, 2 CTA/SM ---
    {
        dim3 g(S_LEN / 64, NB * NH);
        flash_mma_kernel<<<g, 128, FLASH_SMEM>>>(qh, ql, a1);
    }

    // --- Stage 3: out = att @ w_proj + b (att already split in a1) ---
    {
        dim3 gt(CDIM / 32, CDIM / 32), bt(32, 8);
        wsplit_kernel<<<gt, bt>>>(w_proj, wt2, CDIM, CDIM);
    }
    {
        dim3 g(CDIM / 128, MTOT / 128);
        mma_gemm_kernel<<<g, 256, GEMM_SMEM>>>(a1, wt2, b_proj, out,
                                               nullptr, nullptr, CDIM, 0);
    }
}

// round 15
// speedup vs baseline: 1.0639x; 1.0118x over previous
#include <cuda_runtime.h>
#include <cuda_bf16.h>
#include <cstdint>
#include <math.h>

#define S_LEN 2048
#define NB    4
#define NH    6
#define HD    128
#define CDIM  768
#define MTOT  (NB * S_LEN)        // 8192 rows
#define KP    (3 * CDIM)          // 2304 = split-K for bf16x3 GEMM
#define GCH   64                  // GEMM K-chunk (bf16 elems)
#define NCH   (KP / GCH)          // 36 chunks
#define QSCALE 0.08838834764831845f

// ---------------------------------------------------------------------------
// Scratch (device globals: allocation-free rule)
// ---------------------------------------------------------------------------
__device__ __nv_bfloat16 g_a1 [(size_t)MTOT * KP];          // A split [8192, 2304]
__device__ __nv_bfloat16 g_wt1[(size_t)(3 * CDIM) * KP];    // W_attn^T split
__device__ __nv_bfloat16 g_wt2[(size_t)CDIM * KP];          // W_proj^T split
__device__ __nv_bfloat16 g_qh [(size_t)MTOT * (3 * CDIM)];  // QKV hi plane
__device__ __nv_bfloat16 g_ql [(size_t)MTOT * (3 * CDIM)];  // QKV lo plane

__device__ __forceinline__ uint32_t smem_u32(const void* p) {
    uint32_t a;
    asm("{ .reg .u64 t; cvta.to.shared.u64 t, %1; cvt.u32.u64 %0, t; }" : "=r"(a) : "l"(p));
    return a;
}
__device__ __forceinline__ void ldm_x4(uint32_t addr, uint32_t& r0, uint32_t& r1,
                                       uint32_t& r2, uint32_t& r3)
{
    asm volatile("ldmatrix.sync.aligned.m8n8.x4.shared.b16 {%0,%1,%2,%3}, [%4];"
                 : "=r"(r0), "=r"(r1), "=r"(r2), "=r"(r3) : "r"(addr));
}
__device__ __forceinline__ void ldm_x4_t(uint32_t addr, uint32_t& r0, uint32_t& r1,
                                         uint32_t& r2, uint32_t& r3)
{
    asm volatile("ldmatrix.sync.aligned.m8n8.x4.trans.shared.b16 {%0,%1,%2,%3}, [%4];"
                 : "=r"(r0), "=r"(r1), "=r"(r2), "=r"(r3) : "r"(addr));
}
__device__ __forceinline__ void mma16816(float* c, const uint32_t* a, const uint32_t* b)
{
    asm volatile(
        "mma.sync.aligned.m16n8k16.row.col.f32.bf16.bf16.f32 "
        "{%0,%1,%2,%3}, {%4,%5,%6,%7}, {%8,%9}, {%0,%1,%2,%3};"
        : "+f"(c[0]), "+f"(c[1]), "+f"(c[2]), "+f"(c[3])
        : "r"(a[0]), "r"(a[1]), "r"(a[2]), "r"(a[3]), "r"(b[0]), "r"(b[1]));
}
__device__ __forceinline__ uint32_t pack_bf(__nv_bfloat16 lo, __nv_bfloat16 hi) {
    __nv_bfloat162 t(lo, hi);
    return *(uint32_t*)&t;
}

// ---------------------------------------------------------------------------
// Split kernels. A' = [Ah|Al|Ah], B' = [Bh|Bh|Bl] => AhBh + AlBh + AhBl
// asplit vectorized x4: float4 load, uint2 stores per plane (same math).
// ---------------------------------------------------------------------------
__global__ void asplit_kernel(const float* __restrict__ src,
                              __nv_bfloat16* __restrict__ dst, int total, int K)
{
    int i4 = blockIdx.x * blockDim.x + threadIdx.x;
    if (i4 >= total / 4) return;
    const int kq = K / 4;
    int m = i4 / kq, k = (i4 - m * kq) << 2;
    float4 v = ((const float4*)src)[i4];
    __nv_bfloat16 hx = __float2bfloat16_rn(v.x), hy = __float2bfloat16_rn(v.y);
    __nv_bfloat16 hz = __float2bfloat16_rn(v.z), hw = __float2bfloat16_rn(v.w);
    __nv_bfloat16 lx = __float2bfloat16_rn(v.x - __bfloat162float(hx));
    __nv_bfloat16 ly = __float2bfloat16_rn(v.y - __bfloat162float(hy));
    __nv_bfloat16 lz = __float2bfloat16_rn(v.z - __bfloat162float(hz));
    __nv_bfloat16 lw = __float2bfloat16_rn(v.w - __bfloat162float(hw));
    uint2 hp = { pack_bf(hx, hy), pack_bf(hz, hw) };
    uint2 lp = { pack_bf(lx, ly), pack_bf(lz, lw) };
    __nv_bfloat16* d = dst + (size_t)m * (3 * K) + k;
    *(uint2*)(d)         = hp;
    *(uint2*)(d + K)     = lp;
    *(uint2*)(d + 2 * K) = hp;
}

__global__ void wsplit_kernel(const float* __restrict__ W,
                              __nv_bfloat16* __restrict__ Wt, int K, int N)
{
    __shared__ float t[32][33];
    int kb = blockIdx.x * 32, nb = blockIdx.y * 32;
    int tx = threadIdx.x, ty = threadIdx.y;    // block (32, 8)
    for (int i = ty; i < 32; i += 8)
        t[i][tx] = W[(size_t)(kb + i) * N + nb + tx];
    __syncthreads();
    for (int i = ty; i < 32; i += 8) {
        int n = nb + i, k = kb + tx;
        float v = t[tx][i];
        __nv_bfloat16 h = __float2bfloat16_rn(v);
        __nv_bfloat16 l = __float2bfloat16_rn(v - __bfloat162float(h));
        __nv_bfloat16* d = Wt + (size_t)n * (3 * K) + k;
        d[0]     = h;
        d[K]     = h;
        d[2 * K] = l;
    }
}

// ---------------------------------------------------------------------------
// bf16 mma.sync GEMM, 128x128 CTA tile, 3-stage cp.async, 2 CTA/SM.
// Trailing prefetch (issued AFTER the MMA block — measured best placement).
// mode 0: C = f32 out (+bias).   mode 1: hi/lo bf16 planes (+bias), Q scaled.
// ---------------------------------------------------------------------------
#define AST 72
#define STAGE_B  (128 * AST * 2)       // 18432 per operand tile
#define GEMM_SMEM (6 * STAGE_B)        // 110592 (3 stages x A,B)

__device__ __forceinline__ void g_load_tile(uint32_t sm_tile,
                                            const __nv_bfloat16* g, int k0, int tid)
{
#pragma unroll
    for (int i = 0; i < 4; i++) {
        int s = i * 256 + tid;
        int r = s >> 3, cg = s & 7;
        uint32_t dst = sm_tile + r * 144 + cg * 16;
        const void* src = g + (size_t)r * KP + k0 + cg * 8;
        asm volatile("cp.async.cg.shared.global [%0], [%1], 16;" :: "r"(dst), "l"(src));
    }
}

__global__ __launch_bounds__(256, 2) void mma_gemm_kernel(
    const __nv_bfloat16* __restrict__ A1, const __nv_bfloat16* __restrict__ Bt,
    const float* __restrict__ bias, float* __restrict__ C,
    __nv_bfloat16* __restrict__ hiP, __nv_bfloat16* __restrict__ loP,
    int Nt, int mode)
{
    extern __shared__ char smem[];
    const uint32_t sb = smem_u32(smem);
    const int tid = threadIdx.x, wid = tid >> 5, lane = tid & 31;
    const int m0 = blockIdx.y << 7, n0 = blockIdx.x << 7;
    const int wm = wid & 1, wn = wid >> 1;

    const __nv_bfloat16* Ag = A1 + (size_t)m0 * KP;
    const __nv_bfloat16* Bg = Bt + (size_t)n0 * KP;

    float acc[4][4][4];
#pragma unroll
    for (int i = 0; i < 4; i++)
#pragma unroll
        for (int j = 0; j < 4; j++)
#pragma unroll
            for (int r = 0; r < 4; r++) acc[i][j][r] = 0.f;

    const int a_row = (wm << 6) + (lane & 15);
    const int a_kof = (lane >> 4) << 3;
    const int b_row = (wn << 5) + (lane & 7) + (((lane >> 3) >> 1) << 3);
    const int b_kof = ((lane >> 3) & 1) << 3;

    // prologue: chunks 0,1 into stages 0,1
    g_load_tile(sb,                       Ag, 0, tid);
    g_load_tile(sb + 3 * STAGE_B,         Bg, 0, tid);
    asm volatile("cp.async.commit_group;" ::: "memory");
    g_load_tile(sb + STAGE_B,             Ag, GCH, tid);
    g_load_tile(sb + 3 * STAGE_B + STAGE_B, Bg, GCH, tid);
    asm volatile("cp.async.commit_group;" ::: "memory");

    int cur = 0, nxt = 2;     // compute stage, stage for chunk c+2
    for (int c = 0; c < NCH; c++) {
        if (c + 1 < NCH) asm volatile("cp.async.wait_group 1;" ::: "memory");
        else             asm volatile("cp.async.wait_group 0;" ::: "memory");
        __syncthreads();

        const uint32_t sAc = sb + cur * STAGE_B;
        const uint32_t sBc = sb + (3 + cur) * STAGE_B;
#pragma unroll
        for (int ks = 0; ks < 4; ks++) {
            const int kbase = ks << 4;
            uint32_t a[4][4];
#pragma unroll
            for (int mi = 0; mi < 4; mi++) {
                uint32_t addr = sAc + (uint32_t)(a_row + mi * 16) * 144
                              + (uint32_t)(kbase + a_kof) * 2;
                ldm_x4(addr, a[mi][0], a[mi][1], a[mi][2], a[mi][3]);
            }
            uint32_t b[4][2];
#pragma unroll
            for (int nb2 = 0; nb2 < 2; nb2++) {
                uint32_t addr = sBc + (uint32_t)(b_row + nb2 * 16) * 144
                              + (uint32_t)(kbase + b_kof) * 2;
                uint32_t t0, t1, t2, t3;
                ldm_x4(addr, t0, t1, t2, t3);
                b[nb2 * 2 + 0][0] = t0; b[nb2 * 2 + 0][1] = t1;
                b[nb2 * 2 + 1][0] = t2; b[nb2 * 2 + 1][1] = t3;
            }
#pragma unroll
            for (int mi = 0; mi < 4; mi++)
#pragma unroll
                for (int ni = 0; ni < 4; ni++)
                    mma16816(acc[mi][ni], a[mi], b[ni]);
        }

        if (c + 2 < NCH) {
            g_load_tile(sb + nxt * STAGE_B,       Ag, (c + 2) * GCH, tid);
            g_load_tile(sb + (3 + nxt) * STAGE_B, Bg, (c + 2) * GCH, tid);
            asm volatile("cp.async.commit_group;" ::: "memory");
        }
        cur = (cur == 2) ? 0 : cur + 1;
        nxt = (nxt == 2) ? 0 : nxt + 1;
    }

    const int r_top = m0 + (wm << 6) + (lane >> 2);
    const int c_base = n0 + (wn << 5) + ((lane & 3) << 1);
#pragma unroll
    for (int mi = 0; mi < 4; mi++) {
#pragma unroll
        for (int ni = 0; ni < 4; ni++) {
            const int col = c_base + ni * 8;
            const float b0 = bias[col], b1 = bias[col + 1];
            const int row0 = r_top + mi * 16;
            float v00 = acc[mi][ni][0] + b0, v01 = acc[mi][ni][1] + b1;
            float v10 = acc[mi][ni][2] + b0, v11 = acc[mi][ni][3] + b1;
            if (mode == 0) {
                float2 a0 = { v00, v01 }, a1v = { v10, v11 };
                *(float2*)&C[(size_t)row0 * Nt + col]       = a0;
                *(float2*)&C[(size_t)(row0 + 8) * Nt + col] = a1v;
            } else {
                if (col < CDIM) { v00 *= QSCALE; v01 *= QSCALE; v10 *= QSCALE; v11 *= QSCALE; }
                __nv_bfloat16 h00 = __float2bfloat16_rn(v00), h01 = __float2bfloat16_rn(v01);
                __nv_bfloat16 h10 = __float2bfloat16_rn(v10), h11 = __float2bfloat16_rn(v11);
                uint32_t hp0 = pack_bf(h00, h01), hp1 = pack_bf(h10, h11);
                uint32_t lp0 = pack_bf(__float2bfloat16_rn(v00 - __bfloat162float(h00)),
                                       __float2bfloat16_rn(v01 - __bfloat162float(h01)));
                uint32_t lp1 = pack_bf(__float2bfloat16_rn(v10 - __bfloat162float(h10)),
                                       __float2bfloat16_rn(v11 - __bfloat162float(h11)));
                *(uint32_t*)&hiP[(size_t)row0 * Nt + col]       = hp0;
                *(uint32_t*)&loP[(size_t)row0 * Nt + col]       = lp0;
                *(uint32_t*)&hiP[(size_t)(row0 + 8) * Nt + col] = hp1;
                *(uint32_t*)&loP[(size_t)(row0 + 8) * Nt + col] = lp1;
            }
        }
    }
}

// ---------------------------------------------------------------------------
// Tensor-core flash attention (bf16x3, causal). BM=64, BN=64, 128 threads,
// single KV stage, smem 104.4 KB -> 2 CTA/SM, Qh hoisted. (R14 config, frozen.)
// ---------------------------------------------------------------------------
#define FR_STR  272                        // bytes per smem row (136 bf16)
#define OFF_QH  0
#define OFF_QL  (64 * FR_STR)              // 17408
#define OFF_KV0 (2 * 64 * FR_STR)          // 34816
#define SOFF_KH 0
#define SOFF_KL (64 * FR_STR)
#define SOFF_VH (2 * 64 * FR_STR)
#define SOFF_VL (3 * 64 * FR_STR)
#define FLASH_SMEM (OFF_KV0 + 4 * 64 * FR_STR)  // 104448

// one 64x128 bf16 plane tile: 64 rows x 16 chunks of 16B; 8 chunks/thread
__device__ __forceinline__ void stage_plane64(uint32_t dst,
                                              const __nv_bfloat16* src, int tid)
{
#pragma unroll
    for (int i = 0; i < 8; i++) {
        int s = i * 128 + tid;
        int r = s >> 4, c = s & 15;
        asm volatile("cp.async.cg.shared.global [%0], [%1], 16;"
                     :: "r"(dst + r * FR_STR + c * 16),
                        "l"(src + (size_t)r * (3 * CDIM) + c * 8));
    }
}

__global__ __launch_bounds__(128, 2) void flash_mma_kernel(
    const __nv_bfloat16* __restrict__ qh, const __nv_bfloat16* __restrict__ ql,
    __nv_bfloat16* __restrict__ a1out)
{
    extern __shared__ char smc[];
    const uint32_t sb = smem_u32(smc);
    const int tid = threadIdx.x, w = tid >> 5, lane = tid & 31;
    const int b = blockIdx.y / NH, h = blockIdx.y % NH;
    const int p = gridDim.x - 1 - blockIdx.x;     // heaviest first
    const int qm0 = p << 6;                       // 64 q-rows per CTA

    const __nv_bfloat16* qhB = qh + (size_t)(b * S_LEN) * (3 * CDIM) + h * HD;
    const __nv_bfloat16* qlB = ql + (size_t)(b * S_LEN) * (3 * CDIM) + h * HD;
    const int nkb = p + 1;                        // key blocks of 64

    // prologue: Q tiles (hi+lo, 64 rows) + KV block 0
    {
        const __nv_bfloat16* qsrc_h = qhB + (size_t)qm0 * (3 * CDIM);
        const __nv_bfloat16* qsrc_l = qlB + (size_t)qm0 * (3 * CDIM);
#pragma unroll
        for (int i = 0; i < 8; i++) {
            int s = i * 128 + tid;
            int r = s >> 4, c = s & 15;
            asm volatile("cp.async.cg.shared.global [%0], [%1], 16;"
                         :: "r"(sb + OFF_QH + r * FR_STR + c * 16),
                            "l"(qsrc_h + (size_t)r * (3 * CDIM) + c * 8));
            asm volatile("cp.async.cg.shared.global [%0], [%1], 16;"
                         :: "r"(sb + OFF_QL + r * FR_STR + c * 16),
                            "l"(qsrc_l + (size_t)r * (3 * CDIM) + c * 8));
        }
        const uint32_t st0 = sb + OFF_KV0;
        stage_plane64(st0 + SOFF_KH, qhB + CDIM, tid);
        stage_plane64(st0 + SOFF_KL, qlB + CDIM, tid);
        stage_plane64(st0 + SOFF_VH, qhB + 2 * CDIM, tid);
        stage_plane64(st0 + SOFF_VL, qlB + 2 * CDIM, tid);
        asm volatile("cp.async.commit_group;" ::: "memory");
    }

    float m_i[2] = { -1e30f, -1e30f }, l_i[2] = { 0.f, 0.f };
    float o[16][4];
#pragma unroll
    for (int n = 0; n < 16; n++)
#pragma unroll
        for (int r = 0; r < 4; r++) o[n][r] = 0.f;

    const int a_row = (w << 4) + (lane & 15);
    const int a_k8  = (lane >> 4) << 3;
    const int b_row = (lane & 7) + (((lane >> 3) >> 1) << 3);
    const int b_k8  = ((lane >> 3) & 1) << 3;
    const int v_row = lane & 15;
    const int v_n8  = (lane >> 4) << 3;

    const int row_t = qm0 + (w << 4) + (lane >> 2);
    const int col_q = (lane & 3) << 1;

    // wait for Q (and KV0), then hoist Qh fragments into registers
    asm volatile("cp.async.wait_group 0;" ::: "memory");
    __syncthreads();
    uint32_t aQh[8][4];
#pragma unroll
    for (int kt = 0; kt < 8; kt++) {
        const uint32_t koff = (uint32_t)(kt * 16 + a_k8) * 2;
        ldm_x4(sb + OFF_QH + (uint32_t)a_row * FR_STR + koff,
               aQh[kt][0], aQh[kt][1], aQh[kt][2], aQh[kt][3]);
    }

    const uint32_t st = sb + OFF_KV0;
    for (int kb = 0; kb < nkb; kb++) {
        asm volatile("cp.async.wait_group 0;" ::: "memory");
        __syncthreads();   // KV(kb) visible to all warps

        // ---- S = Q'K'^T (3-term bf16, split accumulator banks), 64x64 ----
        float s[8][4], sb2[8][4];
#pragma unroll
        for (int n = 0; n < 8; n++)
#pragma unroll
            for (int r = 0; r < 4; r++) { s[n][r] = 0.f; sb2[n][r] = 0.f; }

#pragma unroll
        for (int kt = 0; kt < 8; kt++) {
            const uint32_t koff = (uint32_t)(kt * 16 + a_k8) * 2;
            uint32_t aL[4];
            ldm_x4(sb + OFF_QL + (uint32_t)a_row * FR_STR + koff,
                   aL[0], aL[1], aL[2], aL[3]);
            const uint32_t kboff = (uint32_t)(kt * 16 + b_k8) * 2;
#pragma unroll
            for (int nb = 0; nb < 4; nb++) {
                uint32_t h0, h1, h2, h3, u0, u1, u2, u3;
                ldm_x4(st + SOFF_KH + (uint32_t)(nb * 16 + b_row) * FR_STR + kboff,
                       h0, h1, h2, h3);
                ldm_x4(st + SOFF_KL + (uint32_t)(nb * 16 + b_row) * FR_STR + kboff,
                       u0, u1, u2, u3);
                uint32_t bh0[2] = { h0, h1 }, bh1[2] = { h2, h3 };
                uint32_t bl0[2] = { u0, u1 }, bl1[2] = { u2, u3 };
                mma16816(s  [2 * nb],     aQh[kt], bh0);
                mma16816(sb2[2 * nb],     aL,      bh0);
                mma16816(sb2[2 * nb],     aQh[kt], bl0);
                mma16816(s  [2 * nb + 1], aQh[kt], bh1);
                mma16816(sb2[2 * nb + 1], aL,      bh1);
                mma16816(sb2[2 * nb + 1], aQh[kt], bl1);
            }
        }
#pragma unroll
        for (int n = 0; n < 8; n++)
#pragma unroll
            for (int r = 0; r < 4; r++) s[n][r] += sb2[n][r];

        // ---- causal mask (diagonal key block only) ----
        if (kb == p) {
            const int col0 = (kb << 6) + col_q;
#pragma unroll
            for (int n = 0; n < 8; n++) {
                const int c = col0 + n * 8;
                if (c     > row_t)     s[n][0] = -1e30f;
                if (c + 1 > row_t)     s[n][1] = -1e30f;
                if (c     > row_t + 8) s[n][2] = -1e30f;
                if (c + 1 > row_t + 8) s[n][3] = -1e30f;
            }
        }

        // ---- online softmax (fp32) ----
        float alpha[2];
#pragma unroll
        for (int hf = 0; hf < 2; hf++) {
            float mx = -1e30f;
#pragma unroll
            for (int n = 0; n < 8; n++)
                mx = fmaxf(mx, fmaxf(s[n][2 * hf], s[n][2 * hf + 1]));
            mx = fmaxf(mx, __shfl_xor_sync(0xffffffffu, mx, 1));
            mx = fmaxf(mx, __shfl_xor_sync(0xffffffffu, mx, 2));
            const float mnew = fmaxf(m_i[hf], mx);
            alpha[hf] = __expf(m_i[hf] - mnew);
            m_i[hf] = mnew;
            float rs = 0.f;
#pragma unroll
            for (int n = 0; n < 8; n++) {
                s[n][2 * hf]     = __expf(s[n][2 * hf]     - mnew);
                s[n][2 * hf + 1] = __expf(s[n][2 * hf + 1] - mnew);
                rs += s[n][2 * hf] + s[n][2 * hf + 1];
            }
            rs += __shfl_xor_sync(0xffffffffu, rs, 1);
            rs += __shfl_xor_sync(0xffffffffu, rs, 2);
            l_i[hf] = l_i[hf] * alpha[hf] + rs;
        }
#pragma unroll
        for (int n = 0; n < 16; n++) {
            o[n][0] *= alpha[0]; o[n][1] *= alpha[0];
            o[n][2] *= alpha[1]; o[n][3] *= alpha[1];
        }

        // ---- P -> bf16 hi/lo A-fragments ----
        uint32_t aPh[4][4], aPl[4][4];
#pragma unroll
        for (int kt = 0; kt < 4; kt++) {
#pragma unroll
            for (int half = 0; half < 2; half++) {
                const int t = 2 * kt + half;
                __nv_bfloat16 h0 = __float2bfloat16_rn(s[t][0]);
                __nv_bfloat16 h1 = __float2bfloat16_rn(s[t][1]);
                __nv_bfloat16 h2 = __float2bfloat16_rn(s[t][2]);
                __nv_bfloat16 h3 = __float2bfloat16_rn(s[t][3]);
                __nv_bfloat16 l0 = __float2bfloat16_rn(s[t][0] - __bfloat162float(h0));
                __nv_bfloat16 l1 = __float2bfloat16_rn(s[t][1] - __bfloat162float(h1));
                __nv_bfloat16 l2 = __float2bfloat16_rn(s[t][2] - __bfloat162float(h2));
                __nv_bfloat16 l3 = __float2bfloat16_rn(s[t][3] - __bfloat162float(h3));
                aPh[kt][2 * half + 0] = pack_bf(h0, h1);
                aPh[kt][2 * half + 1] = pack_bf(h2, h3);
                aPl[kt][2 * half + 0] = pack_bf(l0, l1);
                aPl[kt][2 * half + 1] = pack_bf(l2, l3);
            }
        }

        // ---- O += P'V' (3-term bf16), k=64 ----
#pragma unroll
        for (int kt = 0; kt < 4; kt++) {
            const uint32_t vro = (uint32_t)(kt * 16 + v_row) * FR_STR;
#pragma unroll
            for (int nv = 0; nv < 8; nv++) {
                const uint32_t noff = (uint32_t)(nv * 16 + v_n8) * 2;
                uint32_t h0, h1, h2, h3, u0, u1, u2, u3;
                ldm_x4_t(st + SOFF_VH + vro + noff, h0, h1, h2, h3);
                ldm_x4_t(st + SOFF_VL + vro + noff, u0, u1, u2, u3);
                uint32_t bh0[2] = { h0, h1 }, bh1[2] = { h2, h3 };
                uint32_t bl0[2] = { u0, u1 }, bl1[2] = { u2, u3 };
                mma16816(o[2 * nv],     aPh[kt], bh0);
                mma16816(o[2 * nv],     aPl[kt], bh0);
                mma16816(o[2 * nv],     aPh[kt], bl0);
                mma16816(o[2 * nv + 1], aPh[kt], bh1);
                mma16816(o[2 * nv + 1], aPl[kt], bh1);
                mma16816(o[2 * nv + 1], aPh[kt], bl1);
            }
        }

        __syncthreads();   // all warps done reading KV(kb)
        if (kb + 1 < nkb) {
            const size_t roff = (size_t)((kb + 1) << 6) * (3 * CDIM);
            stage_plane64(st + SOFF_KH, qhB + roff + CDIM, tid);
            stage_plane64(st + SOFF_KL, qlB + roff + CDIM, tid);
            stage_plane64(st + SOFF_VH, qhB + roff + 2 * CDIM, tid);
            stage_plane64(st + SOFF_VL, qlB + roff + 2 * CDIM, tid);
            asm volatile("cp.async.commit_group;" ::: "memory");
        }
    }

    // ---- epilogue: write O directly in split [hi | lo | hi] layout ----
    const float inv0 = 1.f / l_i[0], inv1 = 1.f / l_i[1];
    __nv_bfloat16* ab = a1out + (size_t)(b * S_LEN) * KP + h * HD;
#pragma unroll
    for (int n = 0; n < 16; n++) {
        const int col = n * 8 + col_q;
        float v00 = o[n][0] * inv0, v01 = o[n][1] * inv0;
        float v10 = o[n][2] * inv1, v11 = o[n][3] * inv1;
        __nv_bfloat16 h00 = __float2bfloat16_rn(v00), h01 = __float2bfloat16_rn(v01);
        __nv_bfloat16 h10 = __float2bfloat16_rn(v10), h11 = __float2bfloat16_rn(v11);
        uint32_t hp0 = pack_bf(h00, h01), hp1 = pack_bf(h10, h11);
        uint32_t lp0 = pack_bf(__float2bfloat16_rn(v00 - __bfloat162float(h00)),
                               __float2bfloat16_rn(v01 - __bfloat162float(h01)));
        uint32_t lp1 = pack_bf(__float2bfloat16_rn(v10 - __bfloat162float(h10)),
                               __float2bfloat16_rn(v11 - __bfloat162float(h11)));
        __nv_bfloat16* p0 = ab + (size_t)row_t * KP + col;
        __nv_bfloat16* p1 = ab + (size_t)(row_t + 8) * KP + col;
        *(uint32_t*)(p0)            = hp0;
        *(uint32_t*)(p0 + CDIM)     = lp0;
        *(uint32_t*)(p0 + 2 * CDIM) = hp0;
        *(uint32_t*)(p1)            = hp1;
        *(uint32_t*)(p1 + CDIM)     = lp1;
        *(uint32_t*)(p1 + 2 * CDIM) = hp1;
    }
}

// ---------------------------------------------------------------------------
extern "C" void kernel_launch(void* const* d_in, const int* in_sizes, int n_in,
                              void* d_out, int out_size)
{
    const float* x      = (const float*)d_in[0];
    const float* w_attn = (const float*)d_in[1];
    const float* b_attn = (const float*)d_in[2];
    const float* w_proj = (const float*)d_in[3];
    const float* b_proj = (const float*)d_in[4];
    float* out = (float*)d_out;

    __nv_bfloat16 *a1 = nullptr, *wt1 = nullptr, *wt2 = nullptr, *qh = nullptr, *ql = nullptr;
    cudaGetSymbolAddress((void**)&a1,  g_a1);
    cudaGetSymbolAddress((void**)&wt1, g_wt1);
    cudaGetSymbolAddress((void**)&wt2, g_wt2);
    cudaGetSymbolAddress((void**)&qh,  g_qh);
    cudaGetSymbolAddress((void**)&ql,  g_ql);

    cudaFuncSetAttribute(mma_gemm_kernel,
                         cudaFuncAttributeMaxDynamicSharedMemorySize, GEMM_SMEM);
    cudaFuncSetAttribute(flash_mma_kernel,
                         cudaFuncAttributeMaxDynamicSharedMemorySize, FLASH_SMEM);

    // --- Stage 1: QKV = x @ w_attn + b -> hi/lo planes (Q pre-scaled) ---
    asplit_kernel<<<(MTOT * CDIM / 4 + 255) / 256, 256>>>(x, a1, MTOT * CDIM, CDIM);
    {
        dim3 gt(CDIM / 32, (3 * CDIM) / 32), bt(32, 8);
        wsplit_kernel<<<gt, bt>>>(w_attn, wt1, CDIM, 3 * CDIM);
    }
    {
        dim3 g(3 * CDIM / 128, MTOT / 128);
        mma_gemm_kernel<<<g, 256, GEMM_SMEM>>>(a1, wt1, b_attn, nullptr,
                                               qh, ql, 3 * CDIM, 1);
    }

    // --- Stage 2: causal flash attention (bf16x3), BN=64, 2 CTA/SM ---
    {
        dim3 g(S_LEN / 64, NB * NH);
        flash_mma_kernel<<<g, 128, FLASH_SMEM>>>(qh, ql, a1);
    }

    // --- Stage 3: out = att @ w_proj + b (att already split in a1) ---
    {
        dim3 gt(CDIM / 32, CDIM / 32), bt(32, 8);
        wsplit_kernel<<<gt, bt>>>(w_proj, wt2, CDIM, CDIM);
    }
    {
        dim3 g(CDIM / 128, MTOT / 128);
        mma_gemm_kernel<<<g, 256, GEMM_SMEM>>>(a1, wt2, b_proj, out,
                                               nullptr, nullptr, CDIM, 0);
    }
}

// round 16
// speedup vs baseline: 1.0672x; 1.0031x over previous
#include <cuda_runtime.h>
#include <cuda_bf16.h>
#include <cstdint>
#include <math.h>

#define S_LEN 2048
#define NB    4
#define NH    6
#define HD    128
#define CDIM  768
#define MTOT  (NB * S_LEN)        // 8192 rows
#define KP    (3 * CDIM)          // 2304 = split-K for bf16x3 GEMM
#define GCH   64                  // GEMM K-chunk (bf16 elems)
#define NCH   (KP / GCH)          // 36 chunks
#define QSCALE 0.08838834764831845f

// ---------------------------------------------------------------------------
// Scratch (device globals: allocation-free rule)
// ---------------------------------------------------------------------------
__device__ __nv_bfloat16 g_a1 [(size_t)MTOT * KP];          // A split [8192, 2304]
__device__ __nv_bfloat16 g_wt1[(size_t)(3 * CDIM) * KP];    // W_attn^T split
__device__ __nv_bfloat16 g_wt2[(size_t)CDIM * KP];          // W_proj^T split
__device__ __nv_bfloat16 g_qh [(size_t)MTOT * (3 * CDIM)];  // QKV hi plane
__device__ __nv_bfloat16 g_ql [(size_t)MTOT * (3 * CDIM)];  // QKV lo plane

__device__ __forceinline__ uint32_t smem_u32(const void* p) {
    uint32_t a;
    asm("{ .reg .u64 t; cvta.to.shared.u64 t, %1; cvt.u32.u64 %0, t; }" : "=r"(a) : "l"(p));
    return a;
}
__device__ __forceinline__ void ldm_x4(uint32_t addr, uint32_t& r0, uint32_t& r1,
                                       uint32_t& r2, uint32_t& r3)
{
    asm volatile("ldmatrix.sync.aligned.m8n8.x4.shared.b16 {%0,%1,%2,%3}, [%4];"
                 : "=r"(r0), "=r"(r1), "=r"(r2), "=r"(r3) : "r"(addr));
}
__device__ __forceinline__ void ldm_x4_t(uint32_t addr, uint32_t& r0, uint32_t& r1,
                                         uint32_t& r2, uint32_t& r3)
{
    asm volatile("ldmatrix.sync.aligned.m8n8.x4.trans.shared.b16 {%0,%1,%2,%3}, [%4];"
                 : "=r"(r0), "=r"(r1), "=r"(r2), "=r"(r3) : "r"(addr));
}
__device__ __forceinline__ void mma16816(float* c, const uint32_t* a, const uint32_t* b)
{
    asm volatile(
        "mma.sync.aligned.m16n8k16.row.col.f32.bf16.bf16.f32 "
        "{%0,%1,%2,%3}, {%4,%5,%6,%7}, {%8,%9}, {%0,%1,%2,%3};"
        : "+f"(c[0]), "+f"(c[1]), "+f"(c[2]), "+f"(c[3])
        : "r"(a[0]), "r"(a[1]), "r"(a[2]), "r"(a[3]), "r"(b[0]), "r"(b[1]));
}
__device__ __forceinline__ uint32_t pack_bf(__nv_bfloat16 lo, __nv_bfloat16 hi) {
    __nv_bfloat162 t(lo, hi);
    return *(uint32_t*)&t;
}

// ---------------------------------------------------------------------------
// Split kernels. A' = [Ah|Al|Ah], B' = [Bh|Bh|Bl] => AhBh + AlBh + AhBl
// asplit vectorized x4 (R15). wsplit store phase vectorized x4 (this round).
// ---------------------------------------------------------------------------
__global__ void asplit_kernel(const float* __restrict__ src,
                              __nv_bfloat16* __restrict__ dst, int total, int K)
{
    int i4 = blockIdx.x * blockDim.x + threadIdx.x;
    if (i4 >= total / 4) return;
    const int kq = K / 4;
    int m = i4 / kq, k = (i4 - m * kq) << 2;
    float4 v = ((const float4*)src)[i4];
    __nv_bfloat16 hx = __float2bfloat16_rn(v.x), hy = __float2bfloat16_rn(v.y);
    __nv_bfloat16 hz = __float2bfloat16_rn(v.z), hw = __float2bfloat16_rn(v.w);
    __nv_bfloat16 lx = __float2bfloat16_rn(v.x - __bfloat162float(hx));
    __nv_bfloat16 ly = __float2bfloat16_rn(v.y - __bfloat162float(hy));
    __nv_bfloat16 lz = __float2bfloat16_rn(v.z - __bfloat162float(hz));
    __nv_bfloat16 lw = __float2bfloat16_rn(v.w - __bfloat162float(hw));
    uint2 hp = { pack_bf(hx, hy), pack_bf(hz, hw) };
    uint2 lp = { pack_bf(lx, ly), pack_bf(lz, lw) };
    __nv_bfloat16* d = dst + (size_t)m * (3 * K) + k;
    *(uint2*)(d)         = hp;
    *(uint2*)(d + K)     = lp;
    *(uint2*)(d + 2 * K) = hp;
}

// W[K,N] f32 -> Wt[N, 3K] bf16 K-major: [hi | hi | lo]. 32x32 tiles,
// transpose-staged in smem; store phase emits uint2 (4 k-values) per plane.
__global__ void wsplit_kernel(const float* __restrict__ W,
                              __nv_bfloat16* __restrict__ Wt, int K, int N)
{
    __shared__ float t[32][33];
    int kb = blockIdx.x * 32, nb = blockIdx.y * 32;
    int tx = threadIdx.x, ty = threadIdx.y;    // block (32, 8)
    for (int i = ty; i < 32; i += 8)
        t[i][tx] = W[(size_t)(kb + i) * N + nb + tx];
    __syncthreads();
    // store remap: tid -> (n = tid/8, k-quad q = tid%8)
    const int tid = ty * 32 + tx;
    const int n_loc = tid >> 3, q = tid & 7;
    const int n = nb + n_loc, k = kb + (q << 2);
    __nv_bfloat16 h[4], l[4];
#pragma unroll
    for (int j = 0; j < 4; j++) {
        float v = t[(q << 2) + j][n_loc];
        h[j] = __float2bfloat16_rn(v);
        l[j] = __float2bfloat16_rn(v - __bfloat162float(h[j]));
    }
    uint2 hp = { pack_bf(h[0], h[1]), pack_bf(h[2], h[3]) };
    uint2 lp = { pack_bf(l[0], l[1]), pack_bf(l[2], l[3]) };
    __nv_bfloat16* d = Wt + (size_t)n * (3 * K) + k;
    *(uint2*)(d)         = hp;
    *(uint2*)(d + K)     = hp;
    *(uint2*)(d + 2 * K) = lp;
}

// ---------------------------------------------------------------------------
// bf16 mma.sync GEMM, 128x128 CTA tile, 3-stage cp.async, 2 CTA/SM.
// Trailing prefetch (measured best placement). mode 0: f32 out (+bias).
// mode 1: hi/lo bf16 planes (+bias), Q cols pre-scaled.
// ---------------------------------------------------------------------------
#define AST 72
#define STAGE_B  (128 * AST * 2)       // 18432 per operand tile
#define GEMM_SMEM (6 * STAGE_B)        // 110592 (3 stages x A,B)

__device__ __forceinline__ void g_load_tile(uint32_t sm_tile,
                                            const __nv_bfloat16* g, int k0, int tid)
{
#pragma unroll
    for (int i = 0; i < 4; i++) {
        int s = i * 256 + tid;
        int r = s >> 3, cg = s & 7;
        uint32_t dst = sm_tile + r * 144 + cg * 16;
        const void* src = g + (size_t)r * KP + k0 + cg * 8;
        asm volatile("cp.async.cg.shared.global [%0], [%1], 16;" :: "r"(dst), "l"(src));
    }
}

__global__ __launch_bounds__(256, 2) void mma_gemm_kernel(
    const __nv_bfloat16* __restrict__ A1, const __nv_bfloat16* __restrict__ Bt,
    const float* __restrict__ bias, float* __restrict__ C,
    __nv_bfloat16* __restrict__ hiP, __nv_bfloat16* __restrict__ loP,
    int Nt, int mode)
{
    extern __shared__ char smem[];
    const uint32_t sb = smem_u32(smem);
    const int tid = threadIdx.x, wid = tid >> 5, lane = tid & 31;
    const int m0 = blockIdx.y << 7, n0 = blockIdx.x << 7;
    const int wm = wid & 1, wn = wid >> 1;

    const __nv_bfloat16* Ag = A1 + (size_t)m0 * KP;
    const __nv_bfloat16* Bg = Bt + (size_t)n0 * KP;

    float acc[4][4][4];
#pragma unroll
    for (int i = 0; i < 4; i++)
#pragma unroll
        for (int j = 0; j < 4; j++)
#pragma unroll
            for (int r = 0; r < 4; r++) acc[i][j][r] = 0.f;

    const int a_row = (wm << 6) + (lane & 15);
    const int a_kof = (lane >> 4) << 3;
    const int b_row = (wn << 5) + (lane & 7) + (((lane >> 3) >> 1) << 3);
    const int b_kof = ((lane >> 3) & 1) << 3;

    // prologue: chunks 0,1 into stages 0,1
    g_load_tile(sb,                       Ag, 0, tid);
    g_load_tile(sb + 3 * STAGE_B,         Bg, 0, tid);
    asm volatile("cp.async.commit_group;" ::: "memory");
    g_load_tile(sb + STAGE_B,             Ag, GCH, tid);
    g_load_tile(sb + 3 * STAGE_B + STAGE_B, Bg, GCH, tid);
    asm volatile("cp.async.commit_group;" ::: "memory");

    int cur = 0, nxt = 2;     // compute stage, stage for chunk c+2
    for (int c = 0; c < NCH; c++) {
        if (c + 1 < NCH) asm volatile("cp.async.wait_group 1;" ::: "memory");
        else             asm volatile("cp.async.wait_group 0;" ::: "memory");
        __syncthreads();

        const uint32_t sAc = sb + cur * STAGE_B;
        const uint32_t sBc = sb + (3 + cur) * STAGE_B;
#pragma unroll
        for (int ks = 0; ks < 4; ks++) {
            const int kbase = ks << 4;
            uint32_t a[4][4];
#pragma unroll
            for (int mi = 0; mi < 4; mi++) {
                uint32_t addr = sAc + (uint32_t)(a_row + mi * 16) * 144
                              + (uint32_t)(kbase + a_kof) * 2;
                ldm_x4(addr, a[mi][0], a[mi][1], a[mi][2], a[mi][3]);
            }
            uint32_t b[4][2];
#pragma unroll
            for (int nb2 = 0; nb2 < 2; nb2++) {
                uint32_t addr = sBc + (uint32_t)(b_row + nb2 * 16) * 144
                              + (uint32_t)(kbase + b_kof) * 2;
                uint32_t t0, t1, t2, t3;
                ldm_x4(addr, t0, t1, t2, t3);
                b[nb2 * 2 + 0][0] = t0; b[nb2 * 2 + 0][1] = t1;
                b[nb2 * 2 + 1][0] = t2; b[nb2 * 2 + 1][1] = t3;
            }
#pragma unroll
            for (int mi = 0; mi < 4; mi++)
#pragma unroll
                for (int ni = 0; ni < 4; ni++)
                    mma16816(acc[mi][ni], a[mi], b[ni]);
        }

        if (c + 2 < NCH) {
            g_load_tile(sb + nxt * STAGE_B,       Ag, (c + 2) * GCH, tid);
            g_load_tile(sb + (3 + nxt) * STAGE_B, Bg, (c + 2) * GCH, tid);
            asm volatile("cp.async.commit_group;" ::: "memory");
        }
        cur = (cur == 2) ? 0 : cur + 1;
        nxt = (nxt == 2) ? 0 : nxt + 1;
    }

    const int r_top = m0 + (wm << 6) + (lane >> 2);
    const int c_base = n0 + (wn << 5) + ((lane & 3) << 1);
#pragma unroll
    for (int mi = 0; mi < 4; mi++) {
#pragma unroll
        for (int ni = 0; ni < 4; ni++) {
            const int col = c_base + ni * 8;
            const float b0 = bias[col], b1 = bias[col + 1];
            const int row0 = r_top + mi * 16;
            float v00 = acc[mi][ni][0] + b0, v01 = acc[mi][ni][1] + b1;
            float v10 = acc[mi][ni][2] + b0, v11 = acc[mi][ni][3] + b1;
            if (mode == 0) {
                float2 a0 = { v00, v01 }, a1v = { v10, v11 };
                *(float2*)&C[(size_t)row0 * Nt + col]       = a0;
                *(float2*)&C[(size_t)(row0 + 8) * Nt + col] = a1v;
            } else {
                if (col < CDIM) { v00 *= QSCALE; v01 *= QSCALE; v10 *= QSCALE; v11 *= QSCALE; }
                __nv_bfloat16 h00 = __float2bfloat16_rn(v00), h01 = __float2bfloat16_rn(v01);
                __nv_bfloat16 h10 = __float2bfloat16_rn(v10), h11 = __float2bfloat16_rn(v11);
                uint32_t hp0 = pack_bf(h00, h01), hp1 = pack_bf(h10, h11);
                uint32_t lp0 = pack_bf(__float2bfloat16_rn(v00 - __bfloat162float(h00)),
                                       __float2bfloat16_rn(v01 - __bfloat162float(h01)));
                uint32_t lp1 = pack_bf(__float2bfloat16_rn(v10 - __bfloat162float(h10)),
                                       __float2bfloat16_rn(v11 - __bfloat162float(h11)));
                *(uint32_t*)&hiP[(size_t)row0 * Nt + col]       = hp0;
                *(uint32_t*)&loP[(size_t)row0 * Nt + col]       = lp0;
                *(uint32_t*)&hiP[(size_t)(row0 + 8) * Nt + col] = hp1;
                *(uint32_t*)&loP[(size_t)(row0 + 8) * Nt + col] = lp1;
            }
        }
    }
}

// ---------------------------------------------------------------------------
// Tensor-core flash attention (bf16x3, causal). BM=64, BN=64, 128 threads,
// single KV stage, smem 104.4 KB -> 2 CTA/SM, Qh hoisted. (R14 config, frozen.)
// ---------------------------------------------------------------------------
#define FR_STR  272                        // bytes per smem row (136 bf16)
#define OFF_QH  0
#define OFF_QL  (64 * FR_STR)              // 17408
#define OFF_KV0 (2 * 64 * FR_STR)          // 34816
#define SOFF_KH 0
#define SOFF_KL (64 * FR_STR)
#define SOFF_VH (2 * 64 * FR_STR)
#define SOFF_VL (3 * 64 * FR_STR)
#define FLASH_SMEM (OFF_KV0 + 4 * 64 * FR_STR)  // 104448

// one 64x128 bf16 plane tile: 64 rows x 16 chunks of 16B; 8 chunks/thread
__device__ __forceinline__ void stage_plane64(uint32_t dst,
                                              const __nv_bfloat16* src, int tid)
{
#pragma unroll
    for (int i = 0; i < 8; i++) {
        int s = i * 128 + tid;
        int r = s >> 4, c = s & 15;
        asm volatile("cp.async.cg.shared.global [%0], [%1], 16;"
                     :: "r"(dst + r * FR_STR + c * 16),
                        "l"(src + (size_t)r * (3 * CDIM) + c * 8));
    }
}

__global__ __launch_bounds__(128, 2) void flash_mma_kernel(
    const __nv_bfloat16* __restrict__ qh, const __nv_bfloat16* __restrict__ ql,
    __nv_bfloat16* __restrict__ a1out)
{
    extern __shared__ char smc[];
    const uint32_t sb = smem_u32(smc);
    const int tid = threadIdx.x, w = tid >> 5, lane = tid & 31;
    const int b = blockIdx.y / NH, h = blockIdx.y % NH;
    const int p = gridDim.x - 1 - blockIdx.x;     // heaviest first
    const int qm0 = p << 6;                       // 64 q-rows per CTA

    const __nv_bfloat16* qhB = qh + (size_t)(b * S_LEN) * (3 * CDIM) + h * HD;
    const __nv_bfloat16* qlB = ql + (size_t)(b * S_LEN) * (3 * CDIM) + h * HD;
    const int nkb = p + 1;                        // key blocks of 64

    // prologue: Q tiles (hi+lo, 64 rows) + KV block 0
    {
        const __nv_bfloat16* qsrc_h = qhB + (size_t)qm0 * (3 * CDIM);
        const __nv_bfloat16* qsrc_l = qlB + (size_t)qm0 * (3 * CDIM);
#pragma unroll
        for (int i = 0; i < 8; i++) {
            int s = i * 128 + tid;
            int r = s >> 4, c = s & 15;
            asm volatile("cp.async.cg.shared.global [%0], [%1], 16;"
                         :: "r"(sb + OFF_QH + r * FR_STR + c * 16),
                            "l"(qsrc_h + (size_t)r * (3 * CDIM) + c * 8));
            asm volatile("cp.async.cg.shared.global [%0], [%1], 16;"
                         :: "r"(sb + OFF_QL + r * FR_STR + c * 16),
                            "l"(qsrc_l + (size_t)r * (3 * CDIM) + c * 8));
        }
        const uint32_t st0 = sb + OFF_KV0;
        stage_plane64(st0 + SOFF_KH, qhB + CDIM, tid);
        stage_plane64(st0 + SOFF_KL, qlB + CDIM, tid);
        stage_plane64(st0 + SOFF_VH, qhB + 2 * CDIM, tid);
        stage_plane64(st0 + SOFF_VL, qlB + 2 * CDIM, tid);
        asm volatile("cp.async.commit_group;" ::: "memory");
    }

    float m_i[2] = { -1e30f, -1e30f }, l_i[2] = { 0.f, 0.f };
    float o[16][4];
#pragma unroll
    for (int n = 0; n < 16; n++)
#pragma unroll
        for (int r = 0; r < 4; r++) o[n][r] = 0.f;

    const int a_row = (w << 4) + (lane & 15);
    const int a_k8  = (lane >> 4) << 3;
    const int b_row = (lane & 7) + (((lane >> 3) >> 1) << 3);
    const int b_k8  = ((lane >> 3) & 1) << 3;
    const int v_row = lane & 15;
    const int v_n8  = (lane >> 4) << 3;

    const int row_t = qm0 + (w << 4) + (lane >> 2);
    const int col_q = (lane & 3) << 1;

    // wait for Q (and KV0), then hoist Qh fragments into registers
    asm volatile("cp.async.wait_group 0;" ::: "memory");
    __syncthreads();
    uint32_t aQh[8][4];
#pragma unroll
    for (int kt = 0; kt < 8; kt++) {
        const uint32_t koff = (uint32_t)(kt * 16 + a_k8) * 2;
        ldm_x4(sb + OFF_QH + (uint32_t)a_row * FR_STR + koff,
               aQh[kt][0], aQh[kt][1], aQh[kt][2], aQh[kt][3]);
    }

    const uint32_t st = sb + OFF_KV0;
    for (int kb = 0; kb < nkb; kb++) {
        asm volatile("cp.async.wait_group 0;" ::: "memory");
        __syncthreads();   // KV(kb) visible to all warps

        // ---- S = Q'K'^T (3-term bf16, split accumulator banks), 64x64 ----
        float s[8][4], sb2[8][4];
#pragma unroll
        for (int n = 0; n < 8; n++)
#pragma unroll
            for (int r = 0; r < 4; r++) { s[n][r] = 0.f; sb2[n][r] = 0.f; }

#pragma unroll
        for (int kt = 0; kt < 8; kt++) {
            const uint32_t koff = (uint32_t)(kt * 16 + a_k8) * 2;
            uint32_t aL[4];
            ldm_x4(sb + OFF_QL + (uint32_t)a_row * FR_STR + koff,
                   aL[0], aL[1], aL[2], aL[3]);
            const uint32_t kboff = (uint32_t)(kt * 16 + b_k8) * 2;
#pragma unroll
            for (int nb = 0; nb < 4; nb++) {
                uint32_t h0, h1, h2, h3, u0, u1, u2, u3;
                ldm_x4(st + SOFF_KH + (uint32_t)(nb * 16 + b_row) * FR_STR + kboff,
                       h0, h1, h2, h3);
                ldm_x4(st + SOFF_KL + (uint32_t)(nb * 16 + b_row) * FR_STR + kboff,
                       u0, u1, u2, u3);
                uint32_t bh0[2] = { h0, h1 }, bh1[2] = { h2, h3 };
                uint32_t bl0[2] = { u0, u1 }, bl1[2] = { u2, u3 };
                mma16816(s  [2 * nb],     aQh[kt], bh0);
                mma16816(sb2[2 * nb],     aL,      bh0);
                mma16816(sb2[2 * nb],     aQh[kt], bl0);
                mma16816(s  [2 * nb + 1], aQh[kt], bh1);
                mma16816(sb2[2 * nb + 1], aL,      bh1);
                mma16816(sb2[2 * nb + 1], aQh[kt], bl1);
            }
        }
#pragma unroll
        for (int n = 0; n < 8; n++)
#pragma unroll
            for (int r = 0; r < 4; r++) s[n][r] += sb2[n][r];

        // ---- causal mask (diagonal key block only) ----
        if (kb == p) {
            const int col0 = (kb << 6) + col_q;
#pragma unroll
            for (int n = 0; n < 8; n++) {
                const int c = col0 + n * 8;
                if (c     > row_t)     s[n][0] = -1e30f;
                if (c + 1 > row_t)     s[n][1] = -1e30f;
                if (c     > row_t + 8) s[n][2] = -1e30f;
                if (c + 1 > row_t + 8) s[n][3] = -1e30f;
            }
        }

        // ---- online softmax (fp32) ----
        float alpha[2];
#pragma unroll
        for (int hf = 0; hf < 2; hf++) {
            float mx = -1e30f;
#pragma unroll
            for (int n = 0; n < 8; n++)
                mx = fmaxf(mx, fmaxf(s[n][2 * hf], s[n][2 * hf + 1]));
            mx = fmaxf(mx, __shfl_xor_sync(0xffffffffu, mx, 1));
            mx = fmaxf(mx, __shfl_xor_sync(0xffffffffu, mx, 2));
            const float mnew = fmaxf(m_i[hf], mx);
            alpha[hf] = __expf(m_i[hf] - mnew);
            m_i[hf] = mnew;
            float rs = 0.f;
#pragma unroll
            for (int n = 0; n < 8; n++) {
                s[n][2 * hf]     = __expf(s[n][2 * hf]     - mnew);
                s[n][2 * hf + 1] = __expf(s[n][2 * hf + 1] - mnew);
                rs += s[n][2 * hf] + s[n][2 * hf + 1];
            }
            rs += __shfl_xor_sync(0xffffffffu, rs, 1);
            rs += __shfl_xor_sync(0xffffffffu, rs, 2);
            l_i[hf] = l_i[hf] * alpha[hf] + rs;
        }
#pragma unroll
        for (int n = 0; n < 16; n++) {
            o[n][0] *= alpha[0]; o[n][1] *= alpha[0];
            o[n][2] *= alpha[1]; o[n][3] *= alpha[1];
        }

        // ---- P -> bf16 hi/lo A-fragments ----
        uint32_t aPh[4][4], aPl[4][4];
#pragma unroll
        for (int kt = 0; kt < 4; kt++) {
#pragma unroll
            for (int half = 0; half < 2; half++) {
                const int t = 2 * kt + half;
                __nv_bfloat16 h0 = __float2bfloat16_rn(s[t][0]);
                __nv_bfloat16 h1 = __float2bfloat16_rn(s[t][1]);
                __nv_bfloat16 h2 = __float2bfloat16_rn(s[t][2]);
                __nv_bfloat16 h3 = __float2bfloat16_rn(s[t][3]);
                __nv_bfloat16 l0 = __float2bfloat16_rn(s[t][0] - __bfloat162float(h0));
                __nv_bfloat16 l1 = __float2bfloat16_rn(s[t][1] - __bfloat162float(h1));
                __nv_bfloat16 l2 = __float2bfloat16_rn(s[t][2] - __bfloat162float(h2));
                __nv_bfloat16 l3 = __float2bfloat16_rn(s[t][3] - __bfloat162float(h3));
                aPh[kt][2 * half + 0] = pack_bf(h0, h1);
                aPh[kt][2 * half + 1] = pack_bf(h2, h3);
                aPl[kt][2 * half + 0] = pack_bf(l0, l1);
                aPl[kt][2 * half + 1] = pack_bf(l2, l3);
            }
        }

        // ---- O += P'V' (3-term bf16), k=64 ----
#pragma unroll
        for (int kt = 0; kt < 4; kt++) {
            const uint32_t vro = (uint32_t)(kt * 16 + v_row) * FR_STR;
#pragma unroll
            for (int nv = 0; nv < 8; nv++) {
                const uint32_t noff = (uint32_t)(nv * 16 + v_n8) * 2;
                uint32_t h0, h1, h2, h3, u0, u1, u2, u3;
                ldm_x4_t(st + SOFF_VH + vro + noff, h0, h1, h2, h3);
                ldm_x4_t(st + SOFF_VL + vro + noff, u0, u1, u2, u3);
                uint32_t bh0[2] = { h0, h1 }, bh1[2] = { h2, h3 };
                uint32_t bl0[2] = { u0, u1 }, bl1[2] = { u2, u3 };
                mma16816(o[2 * nv],     aPh[kt], bh0);
                mma16816(o[2 * nv],     aPl[kt], bh0);
                mma16816(o[2 * nv],     aPh[kt], bl0);
                mma16816(o[2 * nv + 1], aPh[kt], bh1);
                mma16816(o[2 * nv + 1], aPl[kt], bh1);
                mma16816(o[2 * nv + 1], aPh[kt], bl1);
            }
        }

        __syncthreads();   // all warps done reading KV(kb)
        if (kb + 1 < nkb) {
            const size_t roff = (size_t)((kb + 1) << 6) * (3 * CDIM);
            stage_plane64(st + SOFF_KH, qhB + roff + CDIM, tid);
            stage_plane64(st + SOFF_KL, qlB + roff + CDIM, tid);
            stage_plane64(st + SOFF_VH, qhB + roff + 2 * CDIM, tid);
            stage_plane64(st + SOFF_VL, qlB + roff + 2 * CDIM, tid);
            asm volatile("cp.async.commit_group;" ::: "memory");
        }
    }

    // ---- epilogue: write O directly in split [hi | lo | hi] layout ----
    const float inv0 = 1.f / l_i[0], inv1 = 1.f / l_i[1];
    __nv_bfloat16* ab = a1out + (size_t)(b * S_LEN) * KP + h * HD;
#pragma unroll
    for (int n = 0; n < 16; n++) {
        const int col = n * 8 + col_q;
        float v00 = o[n][0] * inv0, v01 = o[n][1] * inv0;
        float v10 = o[n][2] * inv1, v11 = o[n][3] * inv1;
        __nv_bfloat16 h00 = __float2bfloat16_rn(v00), h01 = __float2bfloat16_rn(v01);
        __nv_bfloat16 h10 = __float2bfloat16_rn(v10), h11 = __float2bfloat16_rn(v11);
        uint32_t hp0 = pack_bf(h00, h01), hp1 = pack_bf(h10, h11);
        uint32_t lp0 = pack_bf(__float2bfloat16_rn(v00 - __bfloat162float(h00)),
                               __float2bfloat16_rn(v01 - __bfloat162float(h01)));
        uint32_t lp1 = pack_bf(__float2bfloat16_rn(v10 - __bfloat162float(h10)),
                               __float2bfloat16_rn(v11 - __bfloat162float(h11)));
        __nv_bfloat16* p0 = ab + (size_t)row_t * KP + col;
        __nv_bfloat16* p1 = ab + (size_t)(row_t + 8) * KP + col;
        *(uint32_t*)(p0)            = hp0;
        *(uint32_t*)(p0 + CDIM)     = lp0;
        *(uint32_t*)(p0 + 2 * CDIM) = hp0;
        *(uint32_t*)(p1)            = hp1;
        *(uint32_t*)(p1 + CDIM)     = lp1;
        *(uint32_t*)(p1 + 2 * CDIM) = hp1;
    }
}

// ---------------------------------------------------------------------------
extern "C" void kernel_launch(void* const* d_in, const int* in_sizes, int n_in,
                              void* d_out, int out_size)
{
    const float* x      = (const float*)d_in[0];
    const float* w_attn = (const float*)d_in[1];
    const float* b_attn = (const float*)d_in[2];
    const float* w_proj = (const float*)d_in[3];
    const float* b_proj = (const float*)d_in[4];
    float* out = (float*)d_out;

    __nv_bfloat16 *a1 = nullptr, *wt1 = nullptr, *wt2 = nullptr, *qh = nullptr, *ql = nullptr;
    cudaGetSymbolAddress((void**)&a1,  g_a1);
    cudaGetSymbolAddress((void**)&wt1, g_wt1);
    cudaGetSymbolAddress((void**)&wt2, g_wt2);
    cudaGetSymbolAddress((void**)&qh,  g_qh);
    cudaGetSymbolAddress((void**)&ql,  g_ql);

    cudaFuncSetAttribute(mma_gemm_kernel,
                         cudaFuncAttributeMaxDynamicSharedMemorySize, GEMM_SMEM);
    cudaFuncSetAttribute(flash_mma_kernel,
                         cudaFuncAttributeMaxDynamicSharedMemorySize, FLASH_SMEM);

    // --- Stage 1: QKV = x @ w_attn + b -> hi/lo planes (Q pre-scaled) ---
    asplit_kernel<<<(MTOT * CDIM / 4 + 255) / 256, 256>>>(x, a1, MTOT * CDIM, CDIM);
    {
        dim3 gt(CDIM / 32, (3 * CDIM) / 32), bt(32, 8);
        wsplit_kernel<<<gt, bt>>>(w_attn, wt1, CDIM, 3 * CDIM);
    }
    {
        dim3 g(3 * CDIM / 128, MTOT / 128);
        mma_gemm_kernel<<<g, 256, GEMM_SMEM>>>(a1, wt1, b_attn, nullptr,
                                               qh, ql, 3 * CDIM, 1);
    }

    // --- Stage 2: causal flash attention (bf16x3), BN=64, 2 CTA/SM ---
    {
        dim3 g(S_LEN / 64, NB * NH);
        flash_mma_kernel<<<g, 128, FLASH_SMEM>>>(qh, ql, a1);
    }

    // --- Stage 3: out = att @ w_proj + b (att already split in a1) ---
    {
        dim3 gt(CDIM / 32, CDIM / 32), bt(32, 8);
        wsplit_kernel<<<gt, bt>>>(w_proj, wt2, CDIM, CDIM);
    }
    {
        dim3 g(CDIM / 128, MTOT / 128);
        mma_gemm_kernel<<<g, 256, GEMM_SMEM>>>(a1, wt2, b_proj, out,
                                               nullptr, nullptr, CDIM, 0);
    }
}

// round 17
// speedup vs baseline: 1.0732x; 1.0057x over previous
#include <cuda_runtime.h>
#include <cuda_bf16.h>
#include <cstdint>
#include <math.h>

#define S_LEN 2048
#define NB    4
#define NH    6
#define HD    128
#define CDIM  768
#define MTOT  (NB * S_LEN)        // 8192 rows
#define KP    (3 * CDIM)          // 2304 = split-K for bf16x3 GEMM
#define GCH   64                  // GEMM K-chunk (bf16 elems)
#define NCH   (KP / GCH)          // 36 chunks
#define QSCALE 0.08838834764831845f

// ---------------------------------------------------------------------------
// Scratch (device globals: allocation-free rule)
// ---------------------------------------------------------------------------
__device__ __nv_bfloat16 g_a1 [(size_t)MTOT * KP];          // A split [8192, 2304]
__device__ __nv_bfloat16 g_wt1[(size_t)(3 * CDIM) * KP];    // W_attn^T split
__device__ __nv_bfloat16 g_wt2[(size_t)CDIM * KP];          // W_proj^T split
__device__ __nv_bfloat16 g_qh [(size_t)MTOT * (3 * CDIM)];  // QKV hi plane
__device__ __nv_bfloat16 g_ql [(size_t)MTOT * (3 * CDIM)];  // QKV lo plane

__device__ __forceinline__ uint32_t smem_u32(const void* p) {
    uint32_t a;
    asm("{ .reg .u64 t; cvta.to.shared.u64 t, %1; cvt.u32.u64 %0, t; }" : "=r"(a) : "l"(p));
    return a;
}
__device__ __forceinline__ void ldm_x4(uint32_t addr, uint32_t& r0, uint32_t& r1,
                                       uint32_t& r2, uint32_t& r3)
{
    asm volatile("ldmatrix.sync.aligned.m8n8.x4.shared.b16 {%0,%1,%2,%3}, [%4];"
                 : "=r"(r0), "=r"(r1), "=r"(r2), "=r"(r3) : "r"(addr));
}
__device__ __forceinline__ void ldm_x4_t(uint32_t addr, uint32_t& r0, uint32_t& r1,
                                         uint32_t& r2, uint32_t& r3)
{
    asm volatile("ldmatrix.sync.aligned.m8n8.x4.trans.shared.b16 {%0,%1,%2,%3}, [%4];"
                 : "=r"(r0), "=r"(r1), "=r"(r2), "=r"(r3) : "r"(addr));
}
__device__ __forceinline__ void mma16816(float* c, const uint32_t* a, const uint32_t* b)
{
    asm volatile(
        "mma.sync.aligned.m16n8k16.row.col.f32.bf16.bf16.f32 "
        "{%0,%1,%2,%3}, {%4,%5,%6,%7}, {%8,%9}, {%0,%1,%2,%3};"
        : "+f"(c[0]), "+f"(c[1]), "+f"(c[2]), "+f"(c[3])
        : "r"(a[0]), "r"(a[1]), "r"(a[2]), "r"(a[3]), "r"(b[0]), "r"(b[1]));
}
__device__ __forceinline__ uint32_t pack_bf(__nv_bfloat16 lo, __nv_bfloat16 hi) {
    __nv_bfloat162 t(lo, hi);
    return *(uint32_t*)&t;
}

// ---------------------------------------------------------------------------
// Split kernels. A' = [Ah|Al|Ah], B' = [Bh|Bh|Bl] => AhBh + AlBh + AhBl
// ---------------------------------------------------------------------------
__global__ void asplit_kernel(const float* __restrict__ src,
                              __nv_bfloat16* __restrict__ dst, int total, int K)
{
    int i4 = blockIdx.x * blockDim.x + threadIdx.x;
    if (i4 >= total / 4) return;
    const int kq = K / 4;
    int m = i4 / kq, k = (i4 - m * kq) << 2;
    float4 v = ((const float4*)src)[i4];
    __nv_bfloat16 hx = __float2bfloat16_rn(v.x), hy = __float2bfloat16_rn(v.y);
    __nv_bfloat16 hz = __float2bfloat16_rn(v.z), hw = __float2bfloat16_rn(v.w);
    __nv_bfloat16 lx = __float2bfloat16_rn(v.x - __bfloat162float(hx));
    __nv_bfloat16 ly = __float2bfloat16_rn(v.y - __bfloat162float(hy));
    __nv_bfloat16 lz = __float2bfloat16_rn(v.z - __bfloat162float(hz));
    __nv_bfloat16 lw = __float2bfloat16_rn(v.w - __bfloat162float(hw));
    uint2 hp = { pack_bf(hx, hy), pack_bf(hz, hw) };
    uint2 lp = { pack_bf(lx, ly), pack_bf(lz, lw) };
    __nv_bfloat16* d = dst + (size_t)m * (3 * K) + k;
    *(uint2*)(d)         = hp;
    *(uint2*)(d + K)     = lp;
    *(uint2*)(d + 2 * K) = hp;
}

// W[K,N] f32 -> Wt[N, 3K] bf16 K-major: [hi | hi | lo]. Vectorized stores.
__global__ void wsplit_kernel(const float* __restrict__ W,
                              __nv_bfloat16* __restrict__ Wt, int K, int N)
{
    __shared__ float t[32][33];
    int kb = blockIdx.x * 32, nb = blockIdx.y * 32;
    int tx = threadIdx.x, ty = threadIdx.y;    // block (32, 8)
    for (int i = ty; i < 32; i += 8)
        t[i][tx] = W[(size_t)(kb + i) * N + nb + tx];
    __syncthreads();
    const int tid = ty * 32 + tx;
    const int n_loc = tid >> 3, q = tid & 7;
    const int n = nb + n_loc, k = kb + (q << 2);
    __nv_bfloat16 h[4], l[4];
#pragma unroll
    for (int j = 0; j < 4; j++) {
        float v = t[(q << 2) + j][n_loc];
        h[j] = __float2bfloat16_rn(v);
        l[j] = __float2bfloat16_rn(v - __bfloat162float(h[j]));
    }
    uint2 hp = { pack_bf(h[0], h[1]), pack_bf(h[2], h[3]) };
    uint2 lp = { pack_bf(l[0], l[1]), pack_bf(l[2], l[3]) };
    __nv_bfloat16* d = Wt + (size_t)n * (3 * K) + k;
    *(uint2*)(d)         = hp;
    *(uint2*)(d + K)     = hp;
    *(uint2*)(d + 2 * K) = lp;
}

// ---------------------------------------------------------------------------
// bf16 mma.sync GEMM, 128x128 CTA tile, 3-stage cp.async, 2 CTA/SM.
// Trailing prefetch (measured best). mode 0: f32 out. mode 1: hi/lo planes.
// ---------------------------------------------------------------------------
#define AST 72
#define STAGE_B  (128 * AST * 2)       // 18432 per operand tile
#define GEMM_SMEM (6 * STAGE_B)        // 110592 (3 stages x A,B)

__device__ __forceinline__ void g_load_tile(uint32_t sm_tile,
                                            const __nv_bfloat16* g, int k0, int tid)
{
#pragma unroll
    for (int i = 0; i < 4; i++) {
        int s = i * 256 + tid;
        int r = s >> 3, cg = s & 7;
        uint32_t dst = sm_tile + r * 144 + cg * 16;
        const void* src = g + (size_t)r * KP + k0 + cg * 8;
        asm volatile("cp.async.cg.shared.global [%0], [%1], 16;" :: "r"(dst), "l"(src));
    }
}

__global__ __launch_bounds__(256, 2) void mma_gemm_kernel(
    const __nv_bfloat16* __restrict__ A1, const __nv_bfloat16* __restrict__ Bt,
    const float* __restrict__ bias, float* __restrict__ C,
    __nv_bfloat16* __restrict__ hiP, __nv_bfloat16* __restrict__ loP,
    int Nt, int mode)
{
    extern __shared__ char smem[];
    const uint32_t sb = smem_u32(smem);
    const int tid = threadIdx.x, wid = tid >> 5, lane = tid & 31;
    const int m0 = blockIdx.y << 7, n0 = blockIdx.x << 7;
    const int wm = wid & 1, wn = wid >> 1;

    const __nv_bfloat16* Ag = A1 + (size_t)m0 * KP;
    const __nv_bfloat16* Bg = Bt + (size_t)n0 * KP;

    float acc[4][4][4];
#pragma unroll
    for (int i = 0; i < 4; i++)
#pragma unroll
        for (int j = 0; j < 4; j++)
#pragma unroll
            for (int r = 0; r < 4; r++) acc[i][j][r] = 0.f;

    const int a_row = (wm << 6) + (lane & 15);
    const int a_kof = (lane >> 4) << 3;
    const int b_row = (wn << 5) + (lane & 7) + (((lane >> 3) >> 1) << 3);
    const int b_kof = ((lane >> 3) & 1) << 3;

    // prologue: chunks 0,1 into stages 0,1
    g_load_tile(sb,                       Ag, 0, tid);
    g_load_tile(sb + 3 * STAGE_B,         Bg, 0, tid);
    asm volatile("cp.async.commit_group;" ::: "memory");
    g_load_tile(sb + STAGE_B,             Ag, GCH, tid);
    g_load_tile(sb + 3 * STAGE_B + STAGE_B, Bg, GCH, tid);
    asm volatile("cp.async.commit_group;" ::: "memory");

    int cur = 0, nxt = 2;     // compute stage, stage for chunk c+2
    for (int c = 0; c < NCH; c++) {
        if (c + 1 < NCH) asm volatile("cp.async.wait_group 1;" ::: "memory");
        else             asm volatile("cp.async.wait_group 0;" ::: "memory");
        __syncthreads();

        const uint32_t sAc = sb + cur * STAGE_B;
        const uint32_t sBc = sb + (3 + cur) * STAGE_B;
#pragma unroll
        for (int ks = 0; ks < 4; ks++) {
            const int kbase = ks << 4;
            uint32_t a[4][4];
#pragma unroll
            for (int mi = 0; mi < 4; mi++) {
                uint32_t addr = sAc + (uint32_t)(a_row + mi * 16) * 144
                              + (uint32_t)(kbase + a_kof) * 2;
                ldm_x4(addr, a[mi][0], a[mi][1], a[mi][2], a[mi][3]);
            }
            uint32_t b[4][2];
#pragma unroll
            for (int nb2 = 0; nb2 < 2; nb2++) {
                uint32_t addr = sBc + (uint32_t)(b_row + nb2 * 16) * 144
                              + (uint32_t)(kbase + b_kof) * 2;
                uint32_t t0, t1, t2, t3;
                ldm_x4(addr, t0, t1, t2, t3);
                b[nb2 * 2 + 0][0] = t0; b[nb2 * 2 + 0][1] = t1;
                b[nb2 * 2 + 1][0] = t2; b[nb2 * 2 + 1][1] = t3;
            }
#pragma unroll
            for (int mi = 0; mi < 4; mi++)
#pragma unroll
                for (int ni = 0; ni < 4; ni++)
                    mma16816(acc[mi][ni], a[mi], b[ni]);
        }

        if (c + 2 < NCH) {
            g_load_tile(sb + nxt * STAGE_B,       Ag, (c + 2) * GCH, tid);
            g_load_tile(sb + (3 + nxt) * STAGE_B, Bg, (c + 2) * GCH, tid);
            asm volatile("cp.async.commit_group;" ::: "memory");
        }
        cur = (cur == 2) ? 0 : cur + 1;
        nxt = (nxt == 2) ? 0 : nxt + 1;
    }

    const int r_top = m0 + (wm << 6) + (lane >> 2);
    const int c_base = n0 + (wn << 5) + ((lane & 3) << 1);
#pragma unroll
    for (int mi = 0; mi < 4; mi++) {
#pragma unroll
        for (int ni = 0; ni < 4; ni++) {
            const int col = c_base + ni * 8;
            const float b0 = bias[col], b1 = bias[col + 1];
            const int row0 = r_top + mi * 16;
            float v00 = acc[mi][ni][0] + b0, v01 = acc[mi][ni][1] + b1;
            float v10 = acc[mi][ni][2] + b0, v11 = acc[mi][ni][3] + b1;
            if (mode == 0) {
                float2 a0 = { v00, v01 }, a1v = { v10, v11 };
                *(float2*)&C[(size_t)row0 * Nt + col]       = a0;
                *(float2*)&C[(size_t)(row0 + 8) * Nt + col] = a1v;
            } else {
                if (col < CDIM) { v00 *= QSCALE; v01 *= QSCALE; v10 *= QSCALE; v11 *= QSCALE; }
                __nv_bfloat16 h00 = __float2bfloat16_rn(v00), h01 = __float2bfloat16_rn(v01);
                __nv_bfloat16 h10 = __float2bfloat16_rn(v10), h11 = __float2bfloat16_rn(v11);
                uint32_t hp0 = pack_bf(h00, h01), hp1 = pack_bf(h10, h11);
                uint32_t lp0 = pack_bf(__float2bfloat16_rn(v00 - __bfloat162float(h00)),
                                       __float2bfloat16_rn(v01 - __bfloat162float(h01)));
                uint32_t lp1 = pack_bf(__float2bfloat16_rn(v10 - __bfloat162float(h10)),
                                       __float2bfloat16_rn(v11 - __bfloat162float(h11)));
                *(uint32_t*)&hiP[(size_t)row0 * Nt + col]       = hp0;
                *(uint32_t*)&loP[(size_t)row0 * Nt + col]       = lp0;
                *(uint32_t*)&hiP[(size_t)(row0 + 8) * Nt + col] = hp1;
                *(uint32_t*)&loP[(size_t)(row0 + 8) * Nt + col] = lp1;
            }
        }
    }
}

// ---------------------------------------------------------------------------
// Tensor-core flash attention (bf16x3, causal). BM=64, BN=64, 128 threads,
// single KV stage, 2 CTA/SM, Qh hoisted. NEW: K and V planes committed as
// SEPARATE cp.async groups; the S-phase runs under wait_group 1 (K ready)
// while V is still in flight, hiding V's load latency behind S + softmax.
// ---------------------------------------------------------------------------
#define FR_STR  272                        // bytes per smem row (136 bf16)
#define OFF_QH  0
#define OFF_QL  (64 * FR_STR)              // 17408
#define OFF_KV0 (2 * 64 * FR_STR)          // 34816
#define SOFF_KH 0
#define SOFF_KL (64 * FR_STR)
#define SOFF_VH (2 * 64 * FR_STR)
#define SOFF_VL (3 * 64 * FR_STR)
#define FLASH_SMEM (OFF_KV0 + 4 * 64 * FR_STR)  // 104448

// one 64x128 bf16 plane tile: 64 rows x 16 chunks of 16B; 8 chunks/thread
__device__ __forceinline__ void stage_plane64(uint32_t dst,
                                              const __nv_bfloat16* src, int tid)
{
#pragma unroll
    for (int i = 0; i < 8; i++) {
        int s = i * 128 + tid;
        int r = s >> 4, c = s & 15;
        asm volatile("cp.async.cg.shared.global [%0], [%1], 16;"
                     :: "r"(dst + r * FR_STR + c * 16),
                        "l"(src + (size_t)r * (3 * CDIM) + c * 8));
    }
}

__global__ __launch_bounds__(128, 2) void flash_mma_kernel(
    const __nv_bfloat16* __restrict__ qh, const __nv_bfloat16* __restrict__ ql,
    __nv_bfloat16* __restrict__ a1out)
{
    extern __shared__ char smc[];
    const uint32_t sb = smem_u32(smc);
    const int tid = threadIdx.x, w = tid >> 5, lane = tid & 31;
    const int b = blockIdx.y / NH, h = blockIdx.y % NH;
    const int p = gridDim.x - 1 - blockIdx.x;     // heaviest first
    const int qm0 = p << 6;                       // 64 q-rows per CTA

    const __nv_bfloat16* qhB = qh + (size_t)(b * S_LEN) * (3 * CDIM) + h * HD;
    const __nv_bfloat16* qlB = ql + (size_t)(b * S_LEN) * (3 * CDIM) + h * HD;
    const int nkb = p + 1;                        // key blocks of 64
    const uint32_t st = sb + OFF_KV0;

    // prologue: group A = Q tiles + K planes(0); group B = V planes(0)
    {
        const __nv_bfloat16* qsrc_h = qhB + (size_t)qm0 * (3 * CDIM);
        const __nv_bfloat16* qsrc_l = qlB + (size_t)qm0 * (3 * CDIM);
#pragma unroll
        for (int i = 0; i < 8; i++) {
            int s = i * 128 + tid;
            int r = s >> 4, c = s & 15;
            asm volatile("cp.async.cg.shared.global [%0], [%1], 16;"
                         :: "r"(sb + OFF_QH + r * FR_STR + c * 16),
                            "l"(qsrc_h + (size_t)r * (3 * CDIM) + c * 8));
            asm volatile("cp.async.cg.shared.global [%0], [%1], 16;"
                         :: "r"(sb + OFF_QL + r * FR_STR + c * 16),
                            "l"(qsrc_l + (size_t)r * (3 * CDIM) + c * 8));
        }
        stage_plane64(st + SOFF_KH, qhB + CDIM, tid);
        stage_plane64(st + SOFF_KL, qlB + CDIM, tid);
        asm volatile("cp.async.commit_group;" ::: "memory");   // group: Q+K(0)
        stage_plane64(st + SOFF_VH, qhB + 2 * CDIM, tid);
        stage_plane64(st + SOFF_VL, qlB + 2 * CDIM, tid);
        asm volatile("cp.async.commit_group;" ::: "memory");   // group: V(0)
    }

    float m_i[2] = { -1e30f, -1e30f }, l_i[2] = { 0.f, 0.f };
    float o[16][4];
#pragma unroll
    for (int n = 0; n < 16; n++)
#pragma unroll
        for (int r = 0; r < 4; r++) o[n][r] = 0.f;

    const int a_row = (w << 4) + (lane & 15);
    const int a_k8  = (lane >> 4) << 3;
    const int b_row = (lane & 7) + (((lane >> 3) >> 1) << 3);
    const int b_k8  = ((lane >> 3) & 1) << 3;
    const int v_row = lane & 15;
    const int v_n8  = (lane >> 4) << 3;

    const int row_t = qm0 + (w << 4) + (lane >> 2);
    const int col_q = (lane & 3) << 1;

    // Q + K(0) ready; hoist Qh fragments (V(0) may still be in flight)
    asm volatile("cp.async.wait_group 1;" ::: "memory");
    __syncthreads();
    uint32_t aQh[8][4];
#pragma unroll
    for (int kt = 0; kt < 8; kt++) {
        const uint32_t koff = (uint32_t)(kt * 16 + a_k8) * 2;
        ldm_x4(sb + OFF_QH + (uint32_t)a_row * FR_STR + koff,
               aQh[kt][0], aQh[kt][1], aQh[kt][2], aQh[kt][3]);
    }

    for (int kb = 0; kb < nkb; kb++) {
        // K(kb) ready (all groups but the trailing V group); V may be in flight
        asm volatile("cp.async.wait_group 1;" ::: "memory");
        __syncthreads();

        // ---- S = Q'K'^T (3-term bf16, split accumulator banks), 64x64 ----
        float s[8][4], sb2[8][4];
#pragma unroll
        for (int n = 0; n < 8; n++)
#pragma unroll
            for (int r = 0; r < 4; r++) { s[n][r] = 0.f; sb2[n][r] = 0.f; }

#pragma unroll
        for (int kt = 0; kt < 8; kt++) {
            const uint32_t koff = (uint32_t)(kt * 16 + a_k8) * 2;
            uint32_t aL[4];
            ldm_x4(sb + OFF_QL + (uint32_t)a_row * FR_STR + koff,
                   aL[0], aL[1], aL[2], aL[3]);
            const uint32_t kboff = (uint32_t)(kt * 16 + b_k8) * 2;
#pragma unroll
            for (int nb = 0; nb < 4; nb++) {
                uint32_t h0, h1, h2, h3, u0, u1, u2, u3;
                ldm_x4(st + SOFF_KH + (uint32_t)(nb * 16 + b_row) * FR_STR + kboff,
                       h0, h1, h2, h3);
                ldm_x4(st + SOFF_KL + (uint32_t)(nb * 16 + b_row) * FR_STR + kboff,
                       u0, u1, u2, u3);
                uint32_t bh0[2] = { h0, h1 }, bh1[2] = { h2, h3 };
                uint32_t bl0[2] = { u0, u1 }, bl1[2] = { u2, u3 };
                mma16816(s  [2 * nb],     aQh[kt], bh0);
                mma16816(sb2[2 * nb],     aL,      bh0);
                mma16816(sb2[2 * nb],     aQh[kt], bl0);
                mma16816(s  [2 * nb + 1], aQh[kt], bh1);
                mma16816(sb2[2 * nb + 1], aL,      bh1);
                mma16816(sb2[2 * nb + 1], aQh[kt], bl1);
            }
        }
#pragma unroll
        for (int n = 0; n < 8; n++)
#pragma unroll
            for (int r = 0; r < 4; r++) s[n][r] += sb2[n][r];

        // ---- causal mask (diagonal key block only) ----
        if (kb == p) {
            const int col0 = (kb << 6) + col_q;
#pragma unroll
            for (int n = 0; n < 8; n++) {
                const int c = col0 + n * 8;
                if (c     > row_t)     s[n][0] = -1e30f;
                if (c + 1 > row_t)     s[n][1] = -1e30f;
                if (c     > row_t + 8) s[n][2] = -1e30f;
                if (c + 1 > row_t + 8) s[n][3] = -1e30f;
            }
        }

        // ---- online softmax (fp32) ----
        float alpha[2];
#pragma unroll
        for (int hf = 0; hf < 2; hf++) {
            float mx = -1e30f;
#pragma unroll
            for (int n = 0; n < 8; n++)
                mx = fmaxf(mx, fmaxf(s[n][2 * hf], s[n][2 * hf + 1]));
            mx = fmaxf(mx, __shfl_xor_sync(0xffffffffu, mx, 1));
            mx = fmaxf(mx, __shfl_xor_sync(0xffffffffu, mx, 2));
            const float mnew = fmaxf(m_i[hf], mx);
            alpha[hf] = __expf(m_i[hf] - mnew);
            m_i[hf] = mnew;
            float rs = 0.f;
#pragma unroll
            for (int n = 0; n < 8; n++) {
                s[n][2 * hf]     = __expf(s[n][2 * hf]     - mnew);
                s[n][2 * hf + 1] = __expf(s[n][2 * hf + 1] - mnew);
                rs += s[n][2 * hf] + s[n][2 * hf + 1];
            }
            rs += __shfl_xor_sync(0xffffffffu, rs, 1);
            rs += __shfl_xor_sync(0xffffffffu, rs, 2);
            l_i[hf] = l_i[hf] * alpha[hf] + rs;
        }
#pragma unroll
        for (int n = 0; n < 16; n++) {
            o[n][0] *= alpha[0]; o[n][1] *= alpha[0];
            o[n][2] *= alpha[1]; o[n][3] *= alpha[1];
        }

        // ---- P -> bf16 hi/lo A-fragments ----
        uint32_t aPh[4][4], aPl[4][4];
#pragma unroll
        for (int kt = 0; kt < 4; kt++) {
#pragma unroll
            for (int half = 0; half < 2; half++) {
                const int t = 2 * kt + half;
                __nv_bfloat16 h0 = __float2bfloat16_rn(s[t][0]);
                __nv_bfloat16 h1 = __float2bfloat16_rn(s[t][1]);
                __nv_bfloat16 h2 = __float2bfloat16_rn(s[t][2]);
                __nv_bfloat16 h3 = __float2bfloat16_rn(s[t][3]);
                __nv_bfloat16 l0 = __float2bfloat16_rn(s[t][0] - __bfloat162float(h0));
                __nv_bfloat16 l1 = __float2bfloat16_rn(s[t][1] - __bfloat162float(h1));
                __nv_bfloat16 l2 = __float2bfloat16_rn(s[t][2] - __bfloat162float(h2));
                __nv_bfloat16 l3 = __float2bfloat16_rn(s[t][3] - __bfloat162float(h3));
                aPh[kt][2 * half + 0] = pack_bf(h0, h1);
                aPh[kt][2 * half + 1] = pack_bf(h2, h3);
                aPl[kt][2 * half + 0] = pack_bf(l0, l1);
                aPl[kt][2 * half + 1] = pack_bf(l2, l3);
            }
        }

        // ---- V(kb) now required: drain remaining group, sync, then PV ----
        asm volatile("cp.async.wait_group 0;" ::: "memory");
        __syncthreads();

        // ---- O += P'V' (3-term bf16), k=64 ----
#pragma unroll
        for (int kt = 0; kt < 4; kt++) {
            const uint32_t vro = (uint32_t)(kt * 16 + v_row) * FR_STR;
#pragma unroll
            for (int nv = 0; nv < 8; nv++) {
                const uint32_t noff = (uint32_t)(nv * 16 + v_n8) * 2;
                uint32_t h0, h1, h2, h3, u0, u1, u2, u3;
                ldm_x4_t(st + SOFF_VH + vro + noff, h0, h1, h2, h3);
                ldm_x4_t(st + SOFF_VL + vro + noff, u0, u1, u2, u3);
                uint32_t bh0[2] = { h0, h1 }, bh1[2] = { h2, h3 };
                uint32_t bl0[2] = { u0, u1 }, bl1[2] = { u2, u3 };
                mma16816(o[2 * nv],     aPh[kt], bh0);
                mma16816(o[2 * nv],     aPl[kt], bh0);
                mma16816(o[2 * nv],     aPh[kt], bl0);
                mma16816(o[2 * nv + 1], aPh[kt], bh1);
                mma16816(o[2 * nv + 1], aPl[kt], bh1);
                mma16816(o[2 * nv + 1], aPh[kt], bl1);
            }
        }

        __syncthreads();   // all warps done reading K/V(kb) before overwrite
        if (kb + 1 < nkb) {
            const size_t roff = (size_t)((kb + 1) << 6) * (3 * CDIM);
            stage_plane64(st + SOFF_KH, qhB + roff + CDIM, tid);
            stage_plane64(st + SOFF_KL, qlB + roff + CDIM, tid);
            asm volatile("cp.async.commit_group;" ::: "memory");  // K(kb+1)
            stage_plane64(st + SOFF_VH, qhB + roff + 2 * CDIM, tid);
            stage_plane64(st + SOFF_VL, qlB + roff + 2 * CDIM, tid);
            asm volatile("cp.async.commit_group;" ::: "memory");  // V(kb+1)
        }
    }

    // ---- epilogue: write O directly in split [hi | lo | hi] layout ----
    const float inv0 = 1.f / l_i[0], inv1 = 1.f / l_i[1];
    __nv_bfloat16* ab = a1out + (size_t)(b * S_LEN) * KP + h * HD;
#pragma unroll
    for (int n = 0; n < 16; n++) {
        const int col = n * 8 + col_q;
        float v00 = o[n][0] * inv0, v01 = o[n][1] * inv0;
        float v10 = o[n][2] * inv1, v11 = o[n][3] * inv1;
        __nv_bfloat16 h00 = __float2bfloat16_rn(v00), h01 = __float2bfloat16_rn(v01);
        __nv_bfloat16 h10 = __float2bfloat16_rn(v10), h11 = __float2bfloat16_rn(v11);
        uint32_t hp0 = pack_bf(h00, h01), hp1 = pack_bf(h10, h11);
        uint32_t lp0 = pack_bf(__float2bfloat16_rn(v00 - __bfloat162float(h00)),
                               __float2bfloat16_rn(v01 - __bfloat162float(h01)));
        uint32_t lp1 = pack_bf(__float2bfloat16_rn(v10 - __bfloat162float(h10)),
                               __float2bfloat16_rn(v11 - __bfloat162float(h11)));
        __nv_bfloat16* p0 = ab + (size_t)row_t * KP + col;
        __nv_bfloat16* p1 = ab + (size_t)(row_t + 8) * KP + col;
        *(uint32_t*)(p0)            = hp0;
        *(uint32_t*)(p0 + CDIM)     = lp0;
        *(uint32_t*)(p0 + 2 * CDIM) = hp0;
        *(uint32_t*)(p1)            = hp1;
        *(uint32_t*)(p1 + CDIM)     = lp1;
        *(uint32_t*)(p1 + 2 * CDIM) = hp1;
    }
}

// ---------------------------------------------------------------------------
extern "C" void kernel_launch(void* const* d_in, const int* in_sizes, int n_in,
                              void* d_out, int out_size)
{
    const float* x      = (const float*)d_in[0];
    const float* w_attn = (const float*)d_in[1];
    const float* b_attn = (const float*)d_in[2];
    const float* w_proj = (const float*)d_in[3];
    const float* b_proj = (const float*)d_in[4];
    float* out = (float*)d_out;

    __nv_bfloat16 *a1 = nullptr, *wt1 = nullptr, *wt2 = nullptr, *qh = nullptr, *ql = nullptr;
    cudaGetSymbolAddress((void**)&a1,  g_a1);
    cudaGetSymbolAddress((void**)&wt1, g_wt1);
    cudaGetSymbolAddress((void**)&wt2, g_wt2);
    cudaGetSymbolAddress((void**)&qh,  g_qh);
    cudaGetSymbolAddress((void**)&ql,  g_ql);

    cudaFuncSetAttribute(mma_gemm_kernel,
                         cudaFuncAttributeMaxDynamicSharedMemorySize, GEMM_SMEM);
    cudaFuncSetAttribute(flash_mma_kernel,
                         cudaFuncAttributeMaxDynamicSharedMemorySize, FLASH_SMEM);

    // --- Stage 1: QKV = x @ w_attn + b -> hi/lo planes (Q pre-scaled) ---
    asplit_kernel<<<(MTOT * CDIM / 4 + 255) / 256, 256>>>(x, a1, MTOT * CDIM, CDIM);
    {
        dim3 gt(CDIM / 32, (3 * CDIM) / 32), bt(32, 8);
        wsplit_kernel<<<gt, bt>>>(w_attn, wt1, CDIM, 3 * CDIM);
    }
    {
        dim3 g(3 * CDIM / 128, MTOT / 128);
        mma_gemm_kernel<<<g, 256, GEMM_SMEM>>>(a1, wt1, b_attn, nullptr,
                                               qh, ql, 3 * CDIM, 1);
    }

    // --- Stage 2: causal flash attention (bf16x3), split K/V wait groups ---
    {
        dim3 g(S_LEN / 64, NB * NH);
        flash_mma_kernel<<<g, 128, FLASH_SMEM>>>(qh, ql, a1);
    }

    // --- Stage 3: out = att @ w_proj + b (att already split in a1) ---
    {
        dim3 gt(CDIM / 32, CDIM / 32), bt(32, 8);
        wsplit_kernel<<<gt, bt>>>(w_proj, wt2, CDIM, CDIM);
    }
    {
        dim3 g(CDIM / 128, MTOT / 128);
        mma_gemm_kernel<<<g, 256, GEMM_SMEM>>>(a1, wt2, b_proj, out,
                                               nullptr, nullptr, CDIM, 0);
    }
}